// round 2
// baseline (speedup 1.0000x reference)
#include <cuda_runtime.h>
#include <cuda_bf16.h>

// Problem constants
#define T_LEN 512
#define B_SZ  32
#define D_IN  512
#define H_SZ  1024
#define G_SZ  4096   // 4*H

// ---------------------------------------------------------------------------
// Scratch (allocation-free: __device__ globals)
//
// g_xg layout: [dir][s][b][g']  with g' = 4*j + gate  (gate order i,f,g,o)
//   For dir=0 (forward)  step s uses x[:, s, :]
//   For dir=1 (backward) step s uses x[:, T-1-s, :]
// g_h: double-buffered hidden state [buf][dir][b][j]
// g_c: cell state [dir][b][j]
// ---------------------------------------------------------------------------
__device__ float g_xg[(size_t)2 * T_LEN * B_SZ * G_SZ];   // 536 MB
__device__ float g_h[2][2][B_SZ][H_SZ];
__device__ float g_c[2][B_SZ][H_SZ];

// ---------------------------------------------------------------------------
// Zero h (both buffers) and c state. Runs every launch (deterministic replay).
// ---------------------------------------------------------------------------
__global__ void init_state_kernel() {
    size_t i = (size_t)blockIdx.x * blockDim.x + threadIdx.x;
    const size_t nh = (size_t)2 * 2 * B_SZ * H_SZ;   // 131072
    const size_t nc = (size_t)2 * B_SZ * H_SZ;       // 65536
    if (i < nh) ((float*)g_h)[i] = 0.0f;
    if (i < nc) ((float*)g_c)[i] = 0.0f;
}

// ---------------------------------------------------------------------------
// Input GEMM: xg[dir][s][b][g'] = sum_d x[b, tphys, d] * W_ih[perm(g')][d]
//                                 + b_ih[perm(g')] + b_hh[perm(g')]
// perm(g') = (g' & 3) * H + (g' >> 2)
// M = T*B = 16384 (rows ordered r = s*B + b), N = 4096, K = 512, 2 dirs.
// Classic 128x128x8 tile, 256 threads, 8x8 register micro-tile.
// ---------------------------------------------------------------------------
__global__ __launch_bounds__(256, 2)
void input_gemm_kernel(const float* __restrict__ x,
                       const float* __restrict__ Wf_ih,
                       const float* __restrict__ bf_ih,
                       const float* __restrict__ bf_hh,
                       const float* __restrict__ Wb_ih,
                       const float* __restrict__ bb_ih,
                       const float* __restrict__ bb_hh)
{
    const int dir = blockIdx.z;
    const float* __restrict__ W  = dir ? Wb_ih : Wf_ih;
    const float* __restrict__ bi = dir ? bb_ih : bf_ih;
    const float* __restrict__ bh = dir ? bb_hh : bf_hh;

    const int m0 = blockIdx.x * 128;
    const int n0 = blockIdx.y * 128;
    const int tid = threadIdx.x;

    __shared__ float As[8][132];   // [kk][m], pad 132 keeps 16B alignment
    __shared__ float Bs[8][132];   // [kk][n]

    // Loader: each thread loads one float4 of A and one of B per k-tile.
    const int lm = tid >> 1;            // 0..127 (row within tile)
    const int lk = (tid & 1) << 2;      // 0 or 4

    const int mg = m0 + lm;
    const int sA = mg >> 5;             // chain step s
    const int bA = mg & 31;             // batch
    const int tp = dir ? (T_LEN - 1 - sA) : sA;
    const float* arow = x + ((size_t)bA * T_LEN + tp) * D_IN;

    const int gp = n0 + lm;             // permuted gate column
    const float* brow = W + ((size_t)((gp & 3) * H_SZ + (gp >> 2))) * D_IN;

    const int ty = tid >> 4;            // 0..15 -> rows ty*8..ty*8+7
    const int tx = tid & 15;            // 0..15 -> cols tx*8..tx*8+7

    float acc[8][8];
    #pragma unroll
    for (int i = 0; i < 8; i++)
        #pragma unroll
        for (int j = 0; j < 8; j++) acc[i][j] = 0.0f;

    for (int k0 = 0; k0 < D_IN; k0 += 8) {
        float4 av = *(const float4*)(arow + k0 + lk);
        float4 bv = *(const float4*)(brow + k0 + lk);
        As[lk + 0][lm] = av.x; As[lk + 1][lm] = av.y;
        As[lk + 2][lm] = av.z; As[lk + 3][lm] = av.w;
        Bs[lk + 0][lm] = bv.x; Bs[lk + 1][lm] = bv.y;
        Bs[lk + 2][lm] = bv.z; Bs[lk + 3][lm] = bv.w;
        __syncthreads();
        #pragma unroll
        for (int kk = 0; kk < 8; kk++) {
            float a[8], b[8];
            *(float4*)&a[0] = *(const float4*)&As[kk][ty * 8];
            *(float4*)&a[4] = *(const float4*)&As[kk][ty * 8 + 4];
            *(float4*)&b[0] = *(const float4*)&Bs[kk][tx * 8];
            *(float4*)&b[4] = *(const float4*)&Bs[kk][tx * 8 + 4];
            #pragma unroll
            for (int i = 0; i < 8; i++)
                #pragma unroll
                for (int j = 0; j < 8; j++)
                    acc[i][j] += a[i] * b[j];
        }
        __syncthreads();
    }

    // Bias (fold b_ih + b_hh once here) and store to xg (permuted layout).
    float bias[8];
    #pragma unroll
    for (int j = 0; j < 8; j++) {
        int g = n0 + tx * 8 + j;
        int orig = (g & 3) * H_SZ + (g >> 2);
        bias[j] = bi[orig] + bh[orig];
    }
    #pragma unroll
    for (int i = 0; i < 8; i++) {
        int m = m0 + ty * 8 + i;
        int s = m >> 5;
        int b = m & 31;
        float* orow = g_xg + (((size_t)dir * T_LEN + s) * B_SZ + b) * G_SZ
                      + n0 + tx * 8;
        float4 o0 = make_float4(acc[i][0] + bias[0], acc[i][1] + bias[1],
                                acc[i][2] + bias[2], acc[i][3] + bias[3]);
        float4 o1 = make_float4(acc[i][4] + bias[4], acc[i][5] + bias[5],
                                acc[i][6] + bias[6], acc[i][7] + bias[7]);
        *(float4*)(orow)     = o0;
        *(float4*)(orow + 4) = o1;
    }
}

// ---------------------------------------------------------------------------
// One recurrence step (both directions via blockIdx.y).
// gates[b][g'] = xg[dir][s][b][g'] + sum_k h_prev[b][k] * W_hh[perm(g')][k]
// Tile: 32 batch x 64 g' (= 16 hidden units).  256 threads.
// Thread (jl, bl) computes all 4 gates of hidden unit j = g0/4 + jl for
// batches 2*bl and 2*bl+1, then does the full LSTM cell update in registers.
// h double-buffered: read buf s&1, write buf (s&1)^1. c owned exclusively.
// ---------------------------------------------------------------------------
__global__ __launch_bounds__(256, 4)
void lstm_step_kernel(const float* __restrict__ Wf_hh,
                      const float* __restrict__ Wb_hh,
                      float* __restrict__ out, int s, int write_hc)
{
    const int dir = blockIdx.y;
    const float* __restrict__ Whh = dir ? Wb_hh : Wf_hh;
    const int g0 = blockIdx.x * 64;

    const float* hprev = &g_h[s & 1][dir][0][0];
    float*       hnext = &g_h[(s & 1) ^ 1][dir][0][0];
    float*       cst   = &g_c[dir][0][0];

    __shared__ float hs[32][34];   // [kk][b]   (pad 34 keeps float2 alignment)
    __shared__ float ws[32][68];   // [kk][g']  (pad 68 keeps float4 alignment)

    const int tid = threadIdx.x;
    const int jl = tid >> 4;       // 0..15
    const int bl = tid & 15;       // 0..15 -> batches 2bl, 2bl+1

    // ws loader: column wg (0..63), k-offsets wk and wk+16
    const int wg = tid >> 2;
    const int wk = (tid & 3) << 2;
    const int gp = g0 + wg;
    const float* wrow = Whh + ((size_t)((gp & 3) * H_SZ + (gp >> 2))) * H_SZ;

    // hs loader: batch hb (0..31), k-offset hk (0..28)
    const int hb = tid >> 3;
    const int hk = (tid & 7) << 2;
    const float* hrow = hprev + hb * H_SZ;

    float acc[4][2] = {{0.f,0.f},{0.f,0.f},{0.f,0.f},{0.f,0.f}};

    for (int k0 = 0; k0 < H_SZ; k0 += 32) {
        float4 hv = *(const float4*)(hrow + k0 + hk);
        hs[hk + 0][hb] = hv.x; hs[hk + 1][hb] = hv.y;
        hs[hk + 2][hb] = hv.z; hs[hk + 3][hb] = hv.w;
        float4 w0 = *(const float4*)(wrow + k0 + wk);
        float4 w1 = *(const float4*)(wrow + k0 + wk + 16);
        ws[wk +  0][wg] = w0.x; ws[wk +  1][wg] = w0.y;
        ws[wk +  2][wg] = w0.z; ws[wk +  3][wg] = w0.w;
        ws[wk + 16][wg] = w1.x; ws[wk + 17][wg] = w1.y;
        ws[wk + 18][wg] = w1.z; ws[wk + 19][wg] = w1.w;
        __syncthreads();
        #pragma unroll
        for (int kk = 0; kk < 32; kk++) {
            float2 h2 = *(const float2*)&hs[kk][bl << 1];
            float4 w4 = *(const float4*)&ws[kk][jl << 2];
            acc[0][0] += w4.x * h2.x;  acc[0][1] += w4.x * h2.y;
            acc[1][0] += w4.y * h2.x;  acc[1][1] += w4.y * h2.y;
            acc[2][0] += w4.z * h2.x;  acc[2][1] += w4.z * h2.y;
            acc[3][0] += w4.w * h2.x;  acc[3][1] += w4.w * h2.y;
        }
        __syncthreads();
    }

    const int j = (g0 >> 2) + jl;                 // hidden unit index
    const int tphys = dir ? (T_LEN - 1 - s) : s;  // physical time for output
    const size_t xgbase = (((size_t)dir * T_LEN + s) * B_SZ) * G_SZ;
    const size_t OUT_HC0 = (size_t)B_SZ * T_LEN * 2 * H_SZ;
    const size_t OUT_HC1 = OUT_HC0 + (size_t)B_SZ * 2 * H_SZ;

    #pragma unroll
    for (int p = 0; p < 2; p++) {
        const int b = (bl << 1) + p;
        const float4 xg4 = *(const float4*)(g_xg + xgbase + (size_t)b * G_SZ
                                            + g0 + (jl << 2));
        float iv = acc[0][p] + xg4.x;
        float fv = acc[1][p] + xg4.y;
        float gv = acc[2][p] + xg4.z;
        float ov = acc[3][p] + xg4.w;
        iv = 1.0f / (1.0f + __expf(-iv));
        fv = 1.0f / (1.0f + __expf(-fv));
        ov = 1.0f / (1.0f + __expf(-ov));
        gv = tanhf(gv);
        float c = fv * cst[b * H_SZ + j] + iv * gv;
        cst[b * H_SZ + j] = c;
        float h = ov * tanhf(c);
        hnext[b * H_SZ + j] = h;
        out[((size_t)b * T_LEN + tphys) * (2 * H_SZ) + (size_t)dir * H_SZ + j] = h;
        if (write_hc && s == T_LEN - 1) {
            out[OUT_HC0 + ((size_t)b * 2 + dir) * H_SZ + j] = h;
            out[OUT_HC1 + ((size_t)b * 2 + dir) * H_SZ + j] = c;
        }
    }
}

// ---------------------------------------------------------------------------
// Launch. Inputs (metadata order):
//  0 x [B,T,D]  1 Wf_ih [4H,D]  2 Wf_hh [4H,H]  3 bf_ih [4H]  4 bf_hh [4H]
//  5 Wb_ih      6 Wb_hh         7 bb_ih         8 bb_hh
// Output: output[B,T,2H] ++ h[B,2,H] ++ c[B,2,H]  (h/c guarded by out_size)
// ---------------------------------------------------------------------------
extern "C" void kernel_launch(void* const* d_in, const int* in_sizes, int n_in,
                              void* d_out, int out_size)
{
    const float* x     = (const float*)d_in[0];
    const float* Wf_ih = (const float*)d_in[1];
    const float* Wf_hh = (const float*)d_in[2];
    const float* bf_ih = (const float*)d_in[3];
    const float* bf_hh = (const float*)d_in[4];
    const float* Wb_ih = (const float*)d_in[5];
    const float* Wb_hh = (const float*)d_in[6];
    const float* bb_ih = (const float*)d_in[7];
    const float* bb_hh = (const float*)d_in[8];
    float* out = (float*)d_out;

    init_state_kernel<<<512, 256>>>();

    dim3 ggrid(16384 / 128, 4096 / 128, 2);   // (128, 32, 2)
    input_gemm_kernel<<<ggrid, 256>>>(x, Wf_ih, bf_ih, bf_hh,
                                      Wb_ih, bb_ih, bb_hh);

    const long long full = (long long)B_SZ * T_LEN * 2 * H_SZ
                         + 2LL * B_SZ * 2 * H_SZ;
    const int write_hc = ((long long)out_size >= full) ? 1 : 0;

    for (int s = 0; s < T_LEN; s++) {
        lstm_step_kernel<<<dim3(64, 2), 256>>>(Wf_hh, Wb_hh, out, s, write_hc);
    }
}

// round 3
// speedup vs baseline: 1.6657x; 1.6657x over previous
#include <cuda_runtime.h>

// Problem constants
#define T_LEN 512
#define B_SZ  32
#define D_IN  512
#define H_SZ  1024
#define G_SZ  4096   // 4*H

// ---------------------------------------------------------------------------
// Scratch (allocation-free: __device__ globals)
// g_xg : [dir][s][b][g']  gate-interleaved input contributions (g' = 4j+gate)
// g_Wt : [dir][k][g']     W_hh transposed + gate-permuted (for coalesced stage)
// g_ht : [buf][dir][j][b] hidden state, TRANSPOSED (b contiguous) for staging
// g_c  : [dir][b][j]      cell state
// ---------------------------------------------------------------------------
__device__ float g_xg[(size_t)2 * T_LEN * B_SZ * G_SZ];   // 536 MB
__device__ float g_Wt[(size_t)2 * H_SZ * G_SZ];           // 33.5 MB
__device__ float g_ht[2][2][H_SZ][B_SZ];
__device__ float g_c[2][B_SZ][H_SZ];

// ---------------------------------------------------------------------------
__global__ void init_state_kernel() {
    size_t i = (size_t)blockIdx.x * blockDim.x + threadIdx.x;
    const size_t nh = (size_t)2 * 2 * H_SZ * B_SZ;   // 131072
    const size_t nc = (size_t)2 * B_SZ * H_SZ;       // 65536
    if (i < nh) ((float*)g_ht)[i] = 0.0f;
    if (i < nc) ((float*)g_c)[i]  = 0.0f;
}

// ---------------------------------------------------------------------------
// One-time W_hh transpose + gate permutation: g_Wt[dir][k][g'] =
//   Whh_dir[(g'&3)*H + (g'>>2)][k].  Coalesced writes, scattered reads (once).
// ---------------------------------------------------------------------------
__global__ void transpose_whh_kernel(const float* __restrict__ Wf,
                                     const float* __restrict__ Wb) {
    size_t idx = (size_t)blockIdx.x * blockDim.x + threadIdx.x;   // [dir][k][g']
    if (idx >= (size_t)2 * H_SZ * G_SZ) return;
    int gp  = (int)(idx & (G_SZ - 1));
    int k   = (int)((idx >> 12) & (H_SZ - 1));
    int dir = (int)(idx >> 22);
    const float* W = dir ? Wb : Wf;
    g_Wt[idx] = W[((size_t)((gp & 3) * H_SZ + (gp >> 2))) * H_SZ + k];
}

// ---------------------------------------------------------------------------
// Input GEMM (unchanged from R2): xg = x @ W_ih^T + b_ih + b_hh, permuted.
// ---------------------------------------------------------------------------
__global__ __launch_bounds__(256, 2)
void input_gemm_kernel(const float* __restrict__ x,
                       const float* __restrict__ Wf_ih,
                       const float* __restrict__ bf_ih,
                       const float* __restrict__ bf_hh,
                       const float* __restrict__ Wb_ih,
                       const float* __restrict__ bb_ih,
                       const float* __restrict__ bb_hh)
{
    const int dir = blockIdx.z;
    const float* __restrict__ W  = dir ? Wb_ih : Wf_ih;
    const float* __restrict__ bi = dir ? bb_ih : bf_ih;
    const float* __restrict__ bh = dir ? bb_hh : bf_hh;

    const int m0 = blockIdx.x * 128;
    const int n0 = blockIdx.y * 128;
    const int tid = threadIdx.x;

    __shared__ float As[8][132];
    __shared__ float Bs[8][132];

    const int lm = tid >> 1;
    const int lk = (tid & 1) << 2;

    const int mg = m0 + lm;
    const int sA = mg >> 5;
    const int bA = mg & 31;
    const int tp = dir ? (T_LEN - 1 - sA) : sA;
    const float* arow = x + ((size_t)bA * T_LEN + tp) * D_IN;

    const int gp = n0 + lm;
    const float* brow = W + ((size_t)((gp & 3) * H_SZ + (gp >> 2))) * D_IN;

    const int ty = tid >> 4;
    const int tx = tid & 15;

    float acc[8][8];
    #pragma unroll
    for (int i = 0; i < 8; i++)
        #pragma unroll
        for (int j = 0; j < 8; j++) acc[i][j] = 0.0f;

    for (int k0 = 0; k0 < D_IN; k0 += 8) {
        float4 av = *(const float4*)(arow + k0 + lk);
        float4 bv = *(const float4*)(brow + k0 + lk);
        As[lk + 0][lm] = av.x; As[lk + 1][lm] = av.y;
        As[lk + 2][lm] = av.z; As[lk + 3][lm] = av.w;
        Bs[lk + 0][lm] = bv.x; Bs[lk + 1][lm] = bv.y;
        Bs[lk + 2][lm] = bv.z; Bs[lk + 3][lm] = bv.w;
        __syncthreads();
        #pragma unroll
        for (int kk = 0; kk < 8; kk++) {
            float a[8], b[8];
            *(float4*)&a[0] = *(const float4*)&As[kk][ty * 8];
            *(float4*)&a[4] = *(const float4*)&As[kk][ty * 8 + 4];
            *(float4*)&b[0] = *(const float4*)&Bs[kk][tx * 8];
            *(float4*)&b[4] = *(const float4*)&Bs[kk][tx * 8 + 4];
            #pragma unroll
            for (int i = 0; i < 8; i++)
                #pragma unroll
                for (int j = 0; j < 8; j++)
                    acc[i][j] += a[i] * b[j];
        }
        __syncthreads();
    }

    float bias[8];
    #pragma unroll
    for (int j = 0; j < 8; j++) {
        int g = n0 + tx * 8 + j;
        int orig = (g & 3) * H_SZ + (g >> 2);
        bias[j] = bi[orig] + bh[orig];
    }
    #pragma unroll
    for (int i = 0; i < 8; i++) {
        int m = m0 + ty * 8 + i;
        int s = m >> 5;
        int b = m & 31;
        float* orow = g_xg + (((size_t)dir * T_LEN + s) * B_SZ + b) * G_SZ
                      + n0 + tx * 8;
        float4 o0 = make_float4(acc[i][0] + bias[0], acc[i][1] + bias[1],
                                acc[i][2] + bias[2], acc[i][3] + bias[3]);
        float4 o1 = make_float4(acc[i][4] + bias[4], acc[i][5] + bias[5],
                                acc[i][6] + bias[6], acc[i][7] + bias[7]);
        *(float4*)(orow)     = o0;
        *(float4*)(orow + 4) = o1;
    }
}

// ---------------------------------------------------------------------------
// Recurrence step, v2.
// CTA tile: 64 gates (16 hidden units) x 32 batch, both dirs via blockIdx.y.
// 256 threads = 4 k-split groups (ks) x 64 "output threads"; each output
// thread owns 8 gates x 4 batches = 32 accumulators (1.5 B LDS per FMA).
// K processed in 8 chunks of 128 rows, register-staged (LDG next chunk
// overlapped with compute of current). Per-ks partials reduced via smem,
// then LSTM cell update done by all 256 threads (2 cells each).
// ---------------------------------------------------------------------------
#define WS_LD 68
#define HS_LD 36
#define PS_LD 33
#define WS_OFF 0
#define HS_OFF (128 * WS_LD)                      // 8704
#define PS_OFF (HS_OFF + 128 * HS_LD)             // 13312
#define SMEM_FLOATS (PS_OFF + 4 * 64 * PS_LD)     // 21760
#define SMEM_BYTES (SMEM_FLOATS * 4)              // 87040

__global__ __launch_bounds__(256, 1)
void lstm_step_kernel(float* __restrict__ out, int s, int write_hc)
{
    extern __shared__ float sm[];
    float* ws = sm + WS_OFF;
    float* hs = sm + HS_OFF;
    float* ps = sm + PS_OFF;

    const int dir = blockIdx.y;
    const int g0  = blockIdx.x * 64;
    const int tid = threadIdx.x;

    const int ks = tid >> 6;        // 0..3  (k-split group)
    const int r  = tid & 63;
    const int jl = r >> 3;          // 0..7  -> gates jl*8..jl*8+7 (local)
    const int bl = r & 7;           // 0..7  -> batches bl*4..bl*4+3

    const float* __restrict__ Wt = g_Wt + (size_t)dir * H_SZ * G_SZ;
    const float* __restrict__ hprev = &g_ht[s & 1][dir][0][0];

    float acc[8][4];
    #pragma unroll
    for (int g = 0; g < 8; g++)
        #pragma unroll
        for (int b = 0; b < 4; b++) acc[g][b] = 0.0f;

    if (s > 0) {
        float4 wreg[8], hreg[4];

        // ---- prologue: load chunk 0 into regs, store to smem ----
        {
            const int k0 = 0;
            #pragma unroll
            for (int i = 0; i < 8; i++) {
                int q = tid + (i << 8);
                wreg[i] = *(const float4*)(Wt + (size_t)(k0 + (q >> 4)) * G_SZ
                                           + g0 + ((q & 15) << 2));
            }
            #pragma unroll
            for (int i = 0; i < 4; i++) {
                int q = tid + (i << 8);
                hreg[i] = *(const float4*)(hprev + (k0 + (q >> 3)) * B_SZ
                                           + ((q & 7) << 2));
            }
            #pragma unroll
            for (int i = 0; i < 8; i++) {
                int q = tid + (i << 8);
                *(float4*)(ws + (q >> 4) * WS_LD + ((q & 15) << 2)) = wreg[i];
            }
            #pragma unroll
            for (int i = 0; i < 4; i++) {
                int q = tid + (i << 8);
                *(float4*)(hs + (q >> 3) * HS_LD + ((q & 7) << 2)) = hreg[i];
            }
        }
        __syncthreads();

        const int row0 = ks << 5;
        for (int c = 0; c < 8; c++) {
            // issue loads for next chunk (latency hidden under compute)
            if (c < 7) {
                const int k0 = (c + 1) << 7;
                #pragma unroll
                for (int i = 0; i < 8; i++) {
                    int q = tid + (i << 8);
                    wreg[i] = *(const float4*)(Wt + (size_t)(k0 + (q >> 4)) * G_SZ
                                               + g0 + ((q & 15) << 2));
                }
                #pragma unroll
                for (int i = 0; i < 4; i++) {
                    int q = tid + (i << 8);
                    hreg[i] = *(const float4*)(hprev + (k0 + (q >> 3)) * B_SZ
                                               + ((q & 7) << 2));
                }
            }
            // compute this chunk: rows [row0, row0+32)
            #pragma unroll 8
            for (int kk = 0; kk < 32; kk++) {
                const float* wrow = ws + (row0 + kk) * WS_LD + (jl << 3);
                float4 w0 = *(const float4*)(wrow);
                float4 w1 = *(const float4*)(wrow + 4);
                float4 hv = *(const float4*)(hs + (row0 + kk) * HS_LD + (bl << 2));
                float wv[8] = {w0.x, w0.y, w0.z, w0.w, w1.x, w1.y, w1.z, w1.w};
                float hb[4] = {hv.x, hv.y, hv.z, hv.w};
                #pragma unroll
                for (int g = 0; g < 8; g++)
                    #pragma unroll
                    for (int b = 0; b < 4; b++)
                        acc[g][b] += wv[g] * hb[b];
            }
            __syncthreads();
            if (c < 7) {
                #pragma unroll
                for (int i = 0; i < 8; i++) {
                    int q = tid + (i << 8);
                    *(float4*)(ws + (q >> 4) * WS_LD + ((q & 15) << 2)) = wreg[i];
                }
                #pragma unroll
                for (int i = 0; i < 4; i++) {
                    int q = tid + (i << 8);
                    *(float4*)(hs + (q >> 3) * HS_LD + ((q & 7) << 2)) = hreg[i];
                }
                __syncthreads();
            }
        }
    }

    // ---- write per-group partials ----
    #pragma unroll
    for (int g = 0; g < 8; g++)
        #pragma unroll
        for (int b = 0; b < 4; b++)
            ps[(ks * 64 + jl * 8 + g) * PS_LD + (bl * 4 + b)] = acc[g][b];
    __syncthreads();

    // ---- reduce + LSTM cell update: 512 cells, 2 per thread ----
    const int tphys = dir ? (T_LEN - 1 - s) : s;
    float* __restrict__ hnext = &g_ht[(s & 1) ^ 1][dir][0][0];
    const size_t OUT_HC0 = (size_t)B_SZ * T_LEN * 2 * H_SZ;
    const size_t OUT_HC1 = OUT_HC0 + (size_t)B_SZ * 2 * H_SZ;
    const size_t xgbase = (((size_t)dir * T_LEN + s) * B_SZ) * G_SZ;

    #pragma unroll
    for (int p = 0; p < 2; p++) {
        const int cid = tid + (p << 8);
        const int b   = cid >> 4;            // 0..31
        const int ul  = cid & 15;            // 0..15 (local hidden unit)
        const int j   = (g0 >> 2) + ul;

        float gsum[4];
        #pragma unroll
        for (int gi = 0; gi < 4; gi++) {
            float v = 0.0f;
            #pragma unroll
            for (int kq = 0; kq < 4; kq++)
                v += ps[(kq * 64 + ul * 4 + gi) * PS_LD + b];
            gsum[gi] = v;
        }

        const float4 xg4 = *(const float4*)(g_xg + xgbase + (size_t)b * G_SZ
                                            + g0 + (ul << 2));
        float iv = gsum[0] + xg4.x;
        float fv = gsum[1] + xg4.y;
        float gv = gsum[2] + xg4.z;
        float ov = gsum[3] + xg4.w;
        iv = 1.0f / (1.0f + __expf(-iv));
        fv = 1.0f / (1.0f + __expf(-fv));
        ov = 1.0f / (1.0f + __expf(-ov));
        gv = tanhf(gv);
        float cc = fv * g_c[dir][b][j] + iv * gv;
        g_c[dir][b][j] = cc;
        float h = ov * tanhf(cc);
        hnext[j * B_SZ + b] = h;
        out[((size_t)b * T_LEN + tphys) * (2 * H_SZ) + (size_t)dir * H_SZ + j] = h;
        if (write_hc && s == T_LEN - 1) {
            out[OUT_HC0 + ((size_t)b * 2 + dir) * H_SZ + j] = h;
            out[OUT_HC1 + ((size_t)b * 2 + dir) * H_SZ + j] = cc;
        }
    }
}

// ---------------------------------------------------------------------------
extern "C" void kernel_launch(void* const* d_in, const int* in_sizes, int n_in,
                              void* d_out, int out_size)
{
    const float* x     = (const float*)d_in[0];
    const float* Wf_ih = (const float*)d_in[1];
    const float* Wf_hh = (const float*)d_in[2];
    const float* bf_ih = (const float*)d_in[3];
    const float* bf_hh = (const float*)d_in[4];
    const float* Wb_ih = (const float*)d_in[5];
    const float* Wb_hh = (const float*)d_in[6];
    const float* bb_ih = (const float*)d_in[7];
    const float* bb_hh = (const float*)d_in[8];
    float* out = (float*)d_out;

    static int smem_set = 0;
    if (!smem_set) {
        cudaFuncSetAttribute(lstm_step_kernel,
                             cudaFuncAttributeMaxDynamicSharedMemorySize,
                             SMEM_BYTES);
        smem_set = 1;
    }

    init_state_kernel<<<512, 256>>>();

    transpose_whh_kernel<<<(2 * H_SZ * G_SZ) / 256, 256>>>(Wf_hh, Wb_hh);

    dim3 ggrid(16384 / 128, 4096 / 128, 2);
    input_gemm_kernel<<<ggrid, 256>>>(x, Wf_ih, bf_ih, bf_hh,
                                      Wb_ih, bb_ih, bb_hh);

    const long long full = (long long)B_SZ * T_LEN * 2 * H_SZ
                         + 2LL * B_SZ * 2 * H_SZ;
    const int write_hc = ((long long)out_size >= full) ? 1 : 0;

    for (int s = 0; s < T_LEN; s++) {
        lstm_step_kernel<<<dim3(64, 2), 256, SMEM_BYTES>>>(out, s, write_hc);
    }
}

// round 4
// speedup vs baseline: 2.6544x; 1.5936x over previous
#include <cuda_runtime.h>
#include <cuda_bf16.h>

// Problem constants
#define T_LEN 512
#define B_SZ  32
#define D_IN  512
#define H_SZ  1024
#define G_SZ  4096   // 4*H

// ---------------------------------------------------------------------------
// Scratch (allocation-free __device__ globals)
// g_xg    : [dir][s][b][g']   fp32 input contributions, g' = 4j+gate (i,f,g,o)
// g_Wfrag : [dir][gtile 512][kstep 64][lane 32] uint4 {b0hi,b0lo,b1hi,b1lo}
//           mma.m16n8k16 B fragments of W_hh (split bf16 hi/lo), where
//           B[k][n] = W_orig[(n&3)*H + (n>>2)][k]   (n = g', k = hidden j)
// g_hfrag : [buf2][dir2][mt2][kstep 64][lane 32][reg 4] uint2 {hi,lo}
//           mma A fragments of h (rows=batch, cols=j), split bf16
// g_c     : fp32 cell state
// ---------------------------------------------------------------------------
__device__ float g_xg[(size_t)2 * T_LEN * B_SZ * G_SZ];       // 536 MB
__device__ uint4 g_Wfrag[(size_t)2 * 512 * 64 * 32];          // 33.5 MB
__device__ uint2 g_hfrag[2 * 2 * 2 * 64 * 32 * 4];            // 1 MB
__device__ float g_c[2][B_SZ][H_SZ];

// ---------------------------------------------------------------------------
__global__ void init_state_kernel() {
    size_t i = (size_t)blockIdx.x * blockDim.x + threadIdx.x;
    const size_t nf = (size_t)2 * 2 * 2 * 64 * 32 * 4 * 2;   // 262144 u32 of hfrag
    const size_t nc = (size_t)2 * B_SZ * H_SZ;               // 65536
    if (i < nf) ((unsigned*)g_hfrag)[i] = 0u;
    if (i < nc) ((float*)g_c)[i] = 0.0f;
}

// ---------------------------------------------------------------------------
// One-time W_hh -> mma B-fragment pack (split bf16).
// idx = (((dir*512 + gt)*64 + kk)*32 + L)
// B frag (16x8, "col"): b0 = rows 2t,2t+1 col g ; b1 = rows 2t+8,2t+9 col g
//   with t = L&3, g = L>>2.  k-row = kk*16 + ... ; n-col = gt*8 + g.
// ---------------------------------------------------------------------------
__device__ __forceinline__ unsigned pack_bf16x2(__nv_bfloat16 a, __nv_bfloat16 b) {
    __nv_bfloat162 v;
    v.x = a; v.y = b;
    return *(unsigned*)&v;
}

__global__ void wfrag_prep_kernel(const float* __restrict__ Wf,
                                  const float* __restrict__ Wb) {
    unsigned idx = blockIdx.x * blockDim.x + threadIdx.x;
    if (idx >= (2u << 20)) return;
    const int L   = idx & 31;
    const int kk  = (idx >> 5) & 63;
    const int gt  = (idx >> 11) & 511;
    const int dir = idx >> 20;
    const float* __restrict__ W = dir ? Wb : Wf;

    const int gp = gt * 8 + (L >> 2);                    // g'
    const int gate_row = (gp & 3) * H_SZ + (gp >> 2);
    const float* row = W + (size_t)gate_row * H_SZ;
    const int t = L & 3;

    float v[4];
    v[0] = row[kk * 16 + 2 * t];
    v[1] = row[kk * 16 + 2 * t + 1];
    v[2] = row[kk * 16 + 2 * t + 8];
    v[3] = row[kk * 16 + 2 * t + 9];
    __nv_bfloat16 hi[4], lo[4];
    #pragma unroll
    for (int i = 0; i < 4; i++) {
        hi[i] = __float2bfloat16(v[i]);
        lo[i] = __float2bfloat16(v[i] - __bfloat162float(hi[i]));
    }
    uint4 o;
    o.x = pack_bf16x2(hi[0], hi[1]);   // b0 hi
    o.y = pack_bf16x2(lo[0], lo[1]);   // b0 lo
    o.z = pack_bf16x2(hi[2], hi[3]);   // b1 hi
    o.w = pack_bf16x2(lo[2], lo[3]);   // b1 lo
    g_Wfrag[idx] = o;
}

// ---------------------------------------------------------------------------
// Input GEMM (unchanged): xg = x @ W_ih^T + b_ih + b_hh, gate-interleaved.
// ---------------------------------------------------------------------------
__global__ __launch_bounds__(256, 2)
void input_gemm_kernel(const float* __restrict__ x,
                       const float* __restrict__ Wf_ih,
                       const float* __restrict__ bf_ih,
                       const float* __restrict__ bf_hh,
                       const float* __restrict__ Wb_ih,
                       const float* __restrict__ bb_ih,
                       const float* __restrict__ bb_hh)
{
    const int dir = blockIdx.z;
    const float* __restrict__ W  = dir ? Wb_ih : Wf_ih;
    const float* __restrict__ bi = dir ? bb_ih : bf_ih;
    const float* __restrict__ bh = dir ? bb_hh : bf_hh;

    const int m0 = blockIdx.x * 128;
    const int n0 = blockIdx.y * 128;
    const int tid = threadIdx.x;

    __shared__ float As[8][132];
    __shared__ float Bs[8][132];

    const int lm = tid >> 1;
    const int lk = (tid & 1) << 2;

    const int mg = m0 + lm;
    const int sA = mg >> 5;
    const int bA = mg & 31;
    const int tp = dir ? (T_LEN - 1 - sA) : sA;
    const float* arow = x + ((size_t)bA * T_LEN + tp) * D_IN;

    const int gp = n0 + lm;
    const float* brow = W + ((size_t)((gp & 3) * H_SZ + (gp >> 2))) * D_IN;

    const int ty = tid >> 4;
    const int tx = tid & 15;

    float acc[8][8];
    #pragma unroll
    for (int i = 0; i < 8; i++)
        #pragma unroll
        for (int j = 0; j < 8; j++) acc[i][j] = 0.0f;

    for (int k0 = 0; k0 < D_IN; k0 += 8) {
        float4 av = *(const float4*)(arow + k0 + lk);
        float4 bv = *(const float4*)(brow + k0 + lk);
        As[lk + 0][lm] = av.x; As[lk + 1][lm] = av.y;
        As[lk + 2][lm] = av.z; As[lk + 3][lm] = av.w;
        Bs[lk + 0][lm] = bv.x; Bs[lk + 1][lm] = bv.y;
        Bs[lk + 2][lm] = bv.z; Bs[lk + 3][lm] = bv.w;
        __syncthreads();
        #pragma unroll
        for (int kk = 0; kk < 8; kk++) {
            float a[8], b[8];
            *(float4*)&a[0] = *(const float4*)&As[kk][ty * 8];
            *(float4*)&a[4] = *(const float4*)&As[kk][ty * 8 + 4];
            *(float4*)&b[0] = *(const float4*)&Bs[kk][tx * 8];
            *(float4*)&b[4] = *(const float4*)&Bs[kk][tx * 8 + 4];
            #pragma unroll
            for (int i = 0; i < 8; i++)
                #pragma unroll
                for (int j = 0; j < 8; j++)
                    acc[i][j] += a[i] * b[j];
        }
        __syncthreads();
    }

    float bias[8];
    #pragma unroll
    for (int j = 0; j < 8; j++) {
        int g = n0 + tx * 8 + j;
        int orig = (g & 3) * H_SZ + (g >> 2);
        bias[j] = bi[orig] + bh[orig];
    }
    #pragma unroll
    for (int i = 0; i < 8; i++) {
        int m = m0 + ty * 8 + i;
        int s = m >> 5;
        int b = m & 31;
        float* orow = g_xg + (((size_t)dir * T_LEN + s) * B_SZ + b) * G_SZ
                      + n0 + tx * 8;
        float4 o0 = make_float4(acc[i][0] + bias[0], acc[i][1] + bias[1],
                                acc[i][2] + bias[2], acc[i][3] + bias[3]);
        float4 o1 = make_float4(acc[i][4] + bias[4], acc[i][5] + bias[5],
                                acc[i][6] + bias[6], acc[i][7] + bias[7]);
        *(float4*)(orow)     = o0;
        *(float4*)(orow + 4) = o1;
    }
}

// ---------------------------------------------------------------------------
// mma.sync m16n8k16 bf16 -> fp32
// ---------------------------------------------------------------------------
__device__ __forceinline__ void mma_bf16(float* c,
                                         unsigned a0, unsigned a1,
                                         unsigned a2, unsigned a3,
                                         unsigned b0, unsigned b1) {
    asm volatile(
        "mma.sync.aligned.m16n8k16.row.col.f32.bf16.bf16.f32 "
        "{%0,%1,%2,%3}, {%4,%5,%6,%7}, {%8,%9}, {%0,%1,%2,%3};"
        : "+f"(c[0]), "+f"(c[1]), "+f"(c[2]), "+f"(c[3])
        : "r"(a0), "r"(a1), "r"(a2), "r"(a3), "r"(b0), "r"(b1));
}

// ---------------------------------------------------------------------------
// Recurrence step, tensor-core version.
// CTA: 64 gates (16 units) x 32 batch, grid (64, 2=dir). 256 thr = 8 warps.
// Warp w covers k-steps [8w, 8w+8); split bf16 3-pass mma accumulates
// partials; cross-warp reduction in smem; R3-style epilogue; h written
// directly into next step's A-fragment layout.
// ---------------------------------------------------------------------------
#define PSW 2432                       // 32 rows * stride 76
#define SMEM_BYTES (8 * PSW * 4)       // 77824

__global__ __launch_bounds__(256, 1)
void lstm_step_kernel(float* __restrict__ out, int s, int write_hc)
{
    extern __shared__ float sm[];
    const int dir = blockIdx.y;
    const int bx  = blockIdx.x;        // g0 = bx*64, kstep for h writes = bx
    const int tid = threadIdx.x;
    const int w   = tid >> 5;
    const int L   = tid & 31;

    const int buf  = s & 1;
    const int nbuf = buf ^ 1;

    // ---- tensor-core mainloop ----
    float acc[2][8][4];
    #pragma unroll
    for (int mt = 0; mt < 2; mt++)
        #pragma unroll
        for (int nt = 0; nt < 8; nt++)
            #pragma unroll
            for (int i = 0; i < 4; i++) acc[mt][nt][i] = 0.0f;

    {
        const uint4* __restrict__ wfb =
            g_Wfrag + ((size_t)dir * 512 + (bx << 3)) * (64 * 32);
        const uint4* __restrict__ afb =
            (const uint4*)g_hfrag + ((size_t)(buf * 2 + dir) * 2) * (64 * 64);

        const int kk0 = w << 3;
        #pragma unroll 2
        for (int kk = kk0; kk < kk0 + 8; kk++) {
            uint4 A[2][2];
            #pragma unroll
            for (int mt = 0; mt < 2; mt++) {
                const uint4* p = afb + ((size_t)mt * 64 + kk) * 64 + L * 2;
                A[mt][0] = p[0];   // {a0hi,a0lo,a1hi,a1lo}
                A[mt][1] = p[1];   // {a2hi,a2lo,a3hi,a3lo}
            }
            #pragma unroll
            for (int nt = 0; nt < 8; nt++) {
                const uint4 wv = wfb[((size_t)nt * 64 + kk) * 32 + L];
                #pragma unroll
                for (int mt = 0; mt < 2; mt++) {
                    // hi*hi
                    mma_bf16(acc[mt][nt], A[mt][0].x, A[mt][0].z,
                             A[mt][1].x, A[mt][1].z, wv.x, wv.z);
                    // loA*hiB
                    mma_bf16(acc[mt][nt], A[mt][0].y, A[mt][0].w,
                             A[mt][1].y, A[mt][1].w, wv.x, wv.z);
                    // hiA*loB
                    mma_bf16(acc[mt][nt], A[mt][0].x, A[mt][0].z,
                             A[mt][1].x, A[mt][1].z, wv.y, wv.w);
                }
            }
        }
    }

    // ---- dump partials to smem ----
    {
        float* psw = sm + w * PSW;
        const int r  = L >> 2;
        const int g2 = (L & 3) * 2;
        #pragma unroll
        for (int mt = 0; mt < 2; mt++)
            #pragma unroll
            for (int nt = 0; nt < 8; nt++) {
                const int row = mt * 16 + r;
                const int g   = nt * 8 + g2;
                *(float2*)&psw[row * 76 + g] =
                    make_float2(acc[mt][nt][0], acc[mt][nt][1]);
                *(float2*)&psw[(row + 8) * 76 + g] =
                    make_float2(acc[mt][nt][2], acc[mt][nt][3]);
            }
    }
    __syncthreads();

    // ---- reduce + LSTM cell update + h fragment writes ----
    const int tphys = dir ? (T_LEN - 1 - s) : s;
    const size_t OUT_HC0 = (size_t)B_SZ * T_LEN * 2 * H_SZ;
    const size_t OUT_HC1 = OUT_HC0 + (size_t)B_SZ * 2 * H_SZ;
    const size_t xgbase = (((size_t)dir * T_LEN + s) * B_SZ) * G_SZ;

    #pragma unroll
    for (int p = 0; p < 2; p++) {
        const int cid = tid + (p << 8);
        const int b   = cid >> 4;            // 0..31
        const int ul  = cid & 15;            // local hidden unit
        const int j   = (bx << 4) + ul;      // global hidden unit

        float4 v = make_float4(0.f, 0.f, 0.f, 0.f);
        #pragma unroll
        for (int ww = 0; ww < 8; ww++) {
            const float4 q = *(const float4*)&sm[ww * PSW + b * 76 + ul * 4];
            v.x += q.x; v.y += q.y; v.z += q.z; v.w += q.w;
        }

        const float4 xg4 = *(const float4*)(g_xg + xgbase + (size_t)b * G_SZ
                                            + (bx << 6) + (ul << 2));
        float iv = v.x + xg4.x;
        float fv = v.y + xg4.y;
        float gv = v.z + xg4.z;
        float ov = v.w + xg4.w;
        iv = 1.0f / (1.0f + __expf(-iv));
        fv = 1.0f / (1.0f + __expf(-fv));
        ov = 1.0f / (1.0f + __expf(-ov));
        gv = tanhf(gv);
        const float cc = fv * g_c[dir][b][j] + iv * gv;
        g_c[dir][b][j] = cc;
        const float h = ov * tanhf(cc);

        out[((size_t)b * T_LEN + tphys) * (2 * H_SZ) + (size_t)dir * H_SZ + j] = h;
        if (write_hc && s == T_LEN - 1) {
            out[OUT_HC0 + ((size_t)b * 2 + dir) * H_SZ + j] = h;
            out[OUT_HC1 + ((size_t)b * 2 + dir) * H_SZ + j] = cc;
        }

        // pack (j, j+1) pair into the A-fragment slot for the next step
        const float hn = __shfl_down_sync(0xffffffffu, h, 1);
        if ((ul & 1) == 0) {
            const __nv_bfloat16 h0 = __float2bfloat16(h);
            const __nv_bfloat16 h1 = __float2bfloat16(hn);
            const __nv_bfloat16 l0 = __float2bfloat16(h  - __bfloat162float(h0));
            const __nv_bfloat16 l1 = __float2bfloat16(hn - __bfloat162float(h1));
            const int mt    = b >> 4;
            const int rowin = b & 15;
            const int reg   = (rowin >> 3) + ((ul >> 3) << 1);
            const int lane2 = (rowin & 7) * 4 + ((ul & 7) >> 1);
            uint2* dst = g_hfrag
                + (((size_t)(nbuf * 2 + dir) * 2 + mt) * 64 + bx) * 128
                + lane2 * 4 + reg;
            *dst = make_uint2(pack_bf16x2(h0, h1), pack_bf16x2(l0, l1));
        }
    }
}

// ---------------------------------------------------------------------------
extern "C" void kernel_launch(void* const* d_in, const int* in_sizes, int n_in,
                              void* d_out, int out_size)
{
    const float* x     = (const float*)d_in[0];
    const float* Wf_ih = (const float*)d_in[1];
    const float* Wf_hh = (const float*)d_in[2];
    const float* bf_ih = (const float*)d_in[3];
    const float* bf_hh = (const float*)d_in[4];
    const float* Wb_ih = (const float*)d_in[5];
    const float* Wb_hh = (const float*)d_in[6];
    const float* bb_ih = (const float*)d_in[7];
    const float* bb_hh = (const float*)d_in[8];
    float* out = (float*)d_out;

    static int smem_set = 0;
    if (!smem_set) {
        cudaFuncSetAttribute(lstm_step_kernel,
                             cudaFuncAttributeMaxDynamicSharedMemorySize,
                             SMEM_BYTES);
        smem_set = 1;
    }

    init_state_kernel<<<1024, 256>>>();

    wfrag_prep_kernel<<<(2 * 512 * 64 * 32) / 256, 256>>>(Wf_hh, Wb_hh);

    dim3 ggrid(16384 / 128, 4096 / 128, 2);
    input_gemm_kernel<<<ggrid, 256>>>(x, Wf_ih, bf_ih, bf_hh,
                                      Wb_ih, bb_ih, bb_hh);

    const long long full = (long long)B_SZ * T_LEN * 2 * H_SZ
                         + 2LL * B_SZ * 2 * H_SZ;
    const int write_hc = ((long long)out_size >= full) ? 1 : 0;

    for (int s = 0; s < T_LEN; s++) {
        lstm_step_kernel<<<dim3(64, 2), 256, SMEM_BYTES>>>(out, s, write_hc);
    }
}

// round 7
// speedup vs baseline: 2.7831x; 1.0485x over previous
#include <cuda_runtime.h>
#include <cuda_bf16.h>

// Problem constants
#define T_LEN 512
#define B_SZ  32
#define D_IN  512
#define H_SZ  1024
#define G_SZ  4096   // 4*H
#define NCTA  128    // persistent grid: 64 gate-tiles x 2 dirs

// ---------------------------------------------------------------------------
// Scratch (allocation-free __device__ globals)
// g_xg  : [dir][s][b][g']  fp32 input contributions, g' = 4j+gate (i,f,g,o)
// g_Whi : [dir][ctile64][nt8][kk64][L32] uint2 {b0hi, b1hi}  (mma B frag, hi)
// g_Wlo : same layout, {b0lo, b1lo}                           (mma B frag, lo)
//         B[k][n] = W_orig[(n&3)*H + (n>>2)][k], n = g', k = hidden j
// g_hfrag: [buf2][dir2][mt2][kk64][lane32][reg4] uint2 {hi,lo} A frags of h
// g_bar : grid barrier counter (zeroed each launch)
// ---------------------------------------------------------------------------
__device__ float g_xg[(size_t)2 * T_LEN * B_SZ * G_SZ];       // 536 MB
__device__ uint2 g_Whi[(size_t)2 * 64 * 8 * 64 * 32];         // 16.8 MB
__device__ uint2 g_Wlo[(size_t)2 * 64 * 8 * 64 * 32];         // 16.8 MB
__device__ uint2 g_hfrag[2 * 2 * 2 * 64 * 32 * 4];            // 1 MB
__device__ unsigned g_bar;

// ---------------------------------------------------------------------------
__global__ void init_state_kernel() {
    if (blockIdx.x == 0 && threadIdx.x == 0) g_bar = 0u;
}

// ---------------------------------------------------------------------------
__device__ __forceinline__ unsigned pack_bf16x2(__nv_bfloat16 a, __nv_bfloat16 b) {
    __nv_bfloat162 v;
    v.x = a; v.y = b;
    return *(unsigned*)&v;
}

// One-time W_hh -> split-bf16 B-fragment pack (hi and lo arrays).
// idx = ((((dir*64 + ctile)*8 + nt)*64 + kk)*32 + L)
__global__ void wfrag_prep_kernel(const float* __restrict__ Wf,
                                  const float* __restrict__ Wb) {
    unsigned idx = blockIdx.x * blockDim.x + threadIdx.x;
    if (idx >= (2u << 20)) return;
    const int L   = idx & 31;
    const int kk  = (idx >> 5) & 63;
    const int nt  = (idx >> 11) & 7;
    const int ct  = (idx >> 14) & 63;
    const int dir = idx >> 20;
    const float* __restrict__ W = dir ? Wb : Wf;

    const int gp = ((ct << 3) + nt) * 8 + (L >> 2);      // g'
    const int gate_row = (gp & 3) * H_SZ + (gp >> 2);
    const float* row = W + (size_t)gate_row * H_SZ;
    const int t = L & 3;

    float v[4];
    v[0] = row[kk * 16 + 2 * t];
    v[1] = row[kk * 16 + 2 * t + 1];
    v[2] = row[kk * 16 + 2 * t + 8];
    v[3] = row[kk * 16 + 2 * t + 9];
    __nv_bfloat16 hi[4], lo[4];
    #pragma unroll
    for (int i = 0; i < 4; i++) {
        hi[i] = __float2bfloat16(v[i]);
        lo[i] = __float2bfloat16(v[i] - __bfloat162float(hi[i]));
    }
    g_Whi[idx] = make_uint2(pack_bf16x2(hi[0], hi[1]), pack_bf16x2(hi[2], hi[3]));
    g_Wlo[idx] = make_uint2(pack_bf16x2(lo[0], lo[1]), pack_bf16x2(lo[2], lo[3]));
}

// ---------------------------------------------------------------------------
// Input GEMM (unchanged): xg = x @ W_ih^T + b_ih + b_hh, gate-interleaved.
// ---------------------------------------------------------------------------
__global__ __launch_bounds__(256, 2)
void input_gemm_kernel(const float* __restrict__ x,
                       const float* __restrict__ Wf_ih,
                       const float* __restrict__ bf_ih,
                       const float* __restrict__ bf_hh,
                       const float* __restrict__ Wb_ih,
                       const float* __restrict__ bb_ih,
                       const float* __restrict__ bb_hh)
{
    const int dir = blockIdx.z;
    const float* __restrict__ W  = dir ? Wb_ih : Wf_ih;
    const float* __restrict__ bi = dir ? bb_ih : bf_ih;
    const float* __restrict__ bh = dir ? bb_hh : bf_hh;

    const int m0 = blockIdx.x * 128;
    const int n0 = blockIdx.y * 128;
    const int tid = threadIdx.x;

    __shared__ float As[8][132];
    __shared__ float Bs[8][132];

    const int lm = tid >> 1;
    const int lk = (tid & 1) << 2;

    const int mg = m0 + lm;
    const int sA = mg >> 5;
    const int bA = mg & 31;
    const int tp = dir ? (T_LEN - 1 - sA) : sA;
    const float* arow = x + ((size_t)bA * T_LEN + tp) * D_IN;

    const int gp = n0 + lm;
    const float* brow = W + ((size_t)((gp & 3) * H_SZ + (gp >> 2))) * D_IN;

    const int ty = tid >> 4;
    const int tx = tid & 15;

    float acc[8][8];
    #pragma unroll
    for (int i = 0; i < 8; i++)
        #pragma unroll
        for (int j = 0; j < 8; j++) acc[i][j] = 0.0f;

    for (int k0 = 0; k0 < D_IN; k0 += 8) {
        float4 av = *(const float4*)(arow + k0 + lk);
        float4 bv = *(const float4*)(brow + k0 + lk);
        As[lk + 0][lm] = av.x; As[lk + 1][lm] = av.y;
        As[lk + 2][lm] = av.z; As[lk + 3][lm] = av.w;
        Bs[lk + 0][lm] = bv.x; Bs[lk + 1][lm] = bv.y;
        Bs[lk + 2][lm] = bv.z; Bs[lk + 3][lm] = bv.w;
        __syncthreads();
        #pragma unroll
        for (int kk = 0; kk < 8; kk++) {
            float a[8], b[8];
            *(float4*)&a[0] = *(const float4*)&As[kk][ty * 8];
            *(float4*)&a[4] = *(const float4*)&As[kk][ty * 8 + 4];
            *(float4*)&b[0] = *(const float4*)&Bs[kk][tx * 8];
            *(float4*)&b[4] = *(const float4*)&Bs[kk][tx * 8 + 4];
            #pragma unroll
            for (int i = 0; i < 8; i++)
                #pragma unroll
                for (int j = 0; j < 8; j++)
                    acc[i][j] += a[i] * b[j];
        }
        __syncthreads();
    }

    float bias[8];
    #pragma unroll
    for (int j = 0; j < 8; j++) {
        int g = n0 + tx * 8 + j;
        int orig = (g & 3) * H_SZ + (g >> 2);
        bias[j] = bi[orig] + bh[orig];
    }
    #pragma unroll
    for (int i = 0; i < 8; i++) {
        int m = m0 + ty * 8 + i;
        int s = m >> 5;
        int b = m & 31;
        float* orow = g_xg + (((size_t)dir * T_LEN + s) * B_SZ + b) * G_SZ
                      + n0 + tx * 8;
        float4 o0 = make_float4(acc[i][0] + bias[0], acc[i][1] + bias[1],
                                acc[i][2] + bias[2], acc[i][3] + bias[3]);
        float4 o1 = make_float4(acc[i][4] + bias[4], acc[i][5] + bias[5],
                                acc[i][6] + bias[6], acc[i][7] + bias[7]);
        *(float4*)(orow)     = o0;
        *(float4*)(orow + 4) = o1;
    }
}

// ---------------------------------------------------------------------------
__device__ __forceinline__ void mma_bf16(float* c,
                                         unsigned a0, unsigned a1,
                                         unsigned a2, unsigned a3,
                                         unsigned b0, unsigned b1) {
    asm volatile(
        "mma.sync.aligned.m16n8k16.row.col.f32.bf16.bf16.f32 "
        "{%0,%1,%2,%3}, {%4,%5,%6,%7}, {%8,%9}, {%0,%1,%2,%3};"
        : "+f"(c[0]), "+f"(c[1]), "+f"(c[2]), "+f"(c[3])
        : "r"(a0), "r"(a1), "r"(a2), "r"(a3), "r"(b0), "r"(b1));
}

// ---------------------------------------------------------------------------
// Persistent bidirectional LSTM: all 512 steps in one kernel.
// Grid 128 = 64 gate-tiles x 2 dirs, 1 CTA/SM (204KB smem). 256 thr = 8 warps,
// warp w owns k-steps [8w, 8w+8). W-hi resident in smem; W-lo streamed from
// L2; h A-fragments (split bf16) double-buffered in global, read with __ldcg
// (L2-only, so the grid barrier needs no L1 coherence assumptions); c in
// registers. Grid barrier per step with a BOUNDED spin: if co-residency were
// ever violated, the kernel produces wrong output and terminates instead of
// hanging the container (a rel_err failure is diagnosable; a timeout is not).
// ---------------------------------------------------------------------------
#define WS_U2   16384                        // 8*64*32 uint2 per CTA (131072 B)
#define PS_OFF  (WS_U2 * 2)                  // float offset of reduce buffer
#define PSW     2432                         // 32 rows * stride 76
#define SMEM_BYTES (WS_U2 * 8 + 8 * PSW * 4) // 131072 + 77824 = 208896

__global__ __launch_bounds__(256, 1)
void lstm_persist_kernel(float* __restrict__ out, int write_hc)
{
    extern __shared__ float sm[];
    uint2* ws = (uint2*)sm;                  // W-hi fragments [nt][kk][L]
    float* ps = sm + PS_OFF;                 // reduce buffer [w][row][g]

    const int dir = blockIdx.x >> 6;
    const int ct  = blockIdx.x & 63;         // gate tile: g' in [ct*64, ct*64+64)
    const int tid = threadIdx.x;
    const int w   = tid >> 5;
    const int L   = tid & 31;

    // load W-hi slice into smem (once)
    {
        const uint2* src = g_Whi + ((size_t)(dir * 64 + ct) << 14);
        for (int i = tid; i < WS_U2; i += 256) ws[i] = src[i];
    }

    // epilogue cell mapping (2 cells per thread)
    int bb[2], ul[2];
    #pragma unroll
    for (int p = 0; p < 2; p++) {
        const int cid = tid + (p << 8);
        bb[p] = cid >> 4;
        ul[p] = cid & 15;
    }
    float creg[2] = {0.0f, 0.0f};

    const size_t OUT_HC0 = (size_t)B_SZ * T_LEN * 2 * H_SZ;
    const size_t OUT_HC1 = OUT_HC0 + (size_t)B_SZ * 2 * H_SZ;
    const uint2* __restrict__ wlo_base =
        g_Wlo + ((size_t)(dir * 64 + ct) << 14);
    unsigned* bar = &g_bar;
    unsigned spin_limit = 50000000u;         // bounded: never hit when resident

    __syncthreads();

    for (int s = 0; s < T_LEN; s++) {
        const int buf  = s & 1;
        const int nbuf = buf ^ 1;

        // prefetch xg for this step's epilogue (hidden under mainloop)
        const size_t xgbase = ((size_t)dir * T_LEN + s) * B_SZ * G_SZ;
        float4 xgv[2];
        #pragma unroll
        for (int p = 0; p < 2; p++)
            xgv[p] = __ldcg((const float4*)(g_xg + xgbase
                            + (size_t)bb[p] * G_SZ + (ct << 6) + (ul[p] << 2)));

        if (s > 0) {
            float acc[2][8][4];
            #pragma unroll
            for (int mt = 0; mt < 2; mt++)
                #pragma unroll
                for (int nt = 0; nt < 8; nt++)
                    #pragma unroll
                    for (int i = 0; i < 4; i++) acc[mt][nt][i] = 0.0f;

            const uint4* afb =
                (const uint4*)g_hfrag + ((size_t)(buf * 2 + dir) * 2) * (64 * 64);

            const int kk0 = w << 3;
            #pragma unroll 2
            for (int kk = kk0; kk < kk0 + 8; kk++) {
                uint4 A[2][2];
                #pragma unroll
                for (int mt = 0; mt < 2; mt++) {
                    const uint4* p = afb + ((size_t)mt * 64 + kk) * 64 + L * 2;
                    A[mt][0] = __ldcg(p);        // L2-only: barrier-coherent
                    A[mt][1] = __ldcg(p + 1);
                }
                uint2 wl[8];
                #pragma unroll
                for (int nt = 0; nt < 8; nt++)
                    wl[nt] = wlo_base[((nt << 6) + kk) * 32 + L];
                #pragma unroll
                for (int nt = 0; nt < 8; nt++) {
                    const uint2 wh = ws[((nt << 6) + kk) * 32 + L];
                    #pragma unroll
                    for (int mt = 0; mt < 2; mt++) {
                        mma_bf16(acc[mt][nt], A[mt][0].x, A[mt][0].z,
                                 A[mt][1].x, A[mt][1].z, wh.x, wh.y);
                        mma_bf16(acc[mt][nt], A[mt][0].y, A[mt][0].w,
                                 A[mt][1].y, A[mt][1].w, wh.x, wh.y);
                        mma_bf16(acc[mt][nt], A[mt][0].x, A[mt][0].z,
                                 A[mt][1].x, A[mt][1].z, wl[nt].x, wl[nt].y);
                    }
                }
            }

            // dump partials
            float* psw = ps + w * PSW;
            const int r  = L >> 2;
            const int g2 = (L & 3) * 2;
            #pragma unroll
            for (int mt = 0; mt < 2; mt++)
                #pragma unroll
                for (int nt = 0; nt < 8; nt++) {
                    const int row = mt * 16 + r;
                    const int g   = nt * 8 + g2;
                    *(float2*)&psw[row * 76 + g] =
                        make_float2(acc[mt][nt][0], acc[mt][nt][1]);
                    *(float2*)&psw[(row + 8) * 76 + g] =
                        make_float2(acc[mt][nt][2], acc[mt][nt][3]);
                }
        }
        __syncthreads();

        // reduce + cell update + h fragment writes
        const int tphys = dir ? (T_LEN - 1 - s) : s;
        #pragma unroll
        for (int p = 0; p < 2; p++) {
            const int b = bb[p];
            const int u = ul[p];
            const int j = (ct << 4) + u;

            float4 v = make_float4(0.f, 0.f, 0.f, 0.f);
            if (s > 0) {
                #pragma unroll
                for (int ww = 0; ww < 8; ww++) {
                    const float4 q = *(const float4*)&ps[ww * PSW + b * 76 + u * 4];
                    v.x += q.x; v.y += q.y; v.z += q.z; v.w += q.w;
                }
            }

            float iv = v.x + xgv[p].x;
            float fv = v.y + xgv[p].y;
            float gv = v.z + xgv[p].z;
            float ov = v.w + xgv[p].w;
            iv = 1.0f / (1.0f + __expf(-iv));
            fv = 1.0f / (1.0f + __expf(-fv));
            ov = 1.0f / (1.0f + __expf(-ov));
            gv = tanhf(gv);
            const float cc = fv * creg[p] + iv * gv;
            creg[p] = cc;
            const float h = ov * tanhf(cc);

            out[((size_t)b * T_LEN + tphys) * (2 * H_SZ) + (size_t)dir * H_SZ + j] = h;
            if (write_hc && s == T_LEN - 1) {
                out[OUT_HC0 + ((size_t)b * 2 + dir) * H_SZ + j] = h;
                out[OUT_HC1 + ((size_t)b * 2 + dir) * H_SZ + j] = cc;
            }

            // pack (j, j+1) into next step's A-fragment slot
            const float hn = __shfl_down_sync(0xffffffffu, h, 1);
            if ((u & 1) == 0) {
                const __nv_bfloat16 h0 = __float2bfloat16(h);
                const __nv_bfloat16 h1 = __float2bfloat16(hn);
                const __nv_bfloat16 l0 = __float2bfloat16(h  - __bfloat162float(h0));
                const __nv_bfloat16 l1 = __float2bfloat16(hn - __bfloat162float(h1));
                const int mt    = b >> 4;
                const int rowin = b & 15;
                const int reg   = (rowin >> 3) + ((u >> 3) << 1);
                const int lane2 = (rowin & 7) * 4 + ((u & 7) >> 1);
                uint2* dst = g_hfrag
                    + (((size_t)(nbuf * 2 + dir) * 2 + mt) * 64 + ct) * 128
                    + lane2 * 4 + reg;
                *dst = make_uint2(pack_bf16x2(h0, h1), pack_bf16x2(l0, l1));
            }
        }

        // grid barrier: all h writes visible before next step's reads.
        // BOUNDED spin: on timeout, give up waiting permanently (wrong result,
        // but guaranteed termination — never a container-killing hang).
        __syncthreads();
        if (tid == 0) {
            __threadfence();
            asm volatile("red.release.gpu.global.add.u32 [%0], 1;"
                         :: "l"(bar) : "memory");
            const unsigned target = (unsigned)(s + 1) * NCTA;
            unsigned vv;
            unsigned it = 0;
            do {
                asm volatile("ld.acquire.gpu.global.u32 %0, [%1];"
                             : "=r"(vv) : "l"(bar) : "memory");
                if (vv >= target) break;
            } while (++it < spin_limit);
            if (it >= spin_limit) spin_limit = 0;   // give up on all later waits
            __threadfence();
        }
        __syncthreads();
    }
}

// ---------------------------------------------------------------------------
extern "C" void kernel_launch(void* const* d_in, const int* in_sizes, int n_in,
                              void* d_out, int out_size)
{
    const float* x     = (const float*)d_in[0];
    const float* Wf_ih = (const float*)d_in[1];
    const float* Wf_hh = (const float*)d_in[2];
    const float* bf_ih = (const float*)d_in[3];
    const float* bf_hh = (const float*)d_in[4];
    const float* Wb_ih = (const float*)d_in[5];
    const float* Wb_hh = (const float*)d_in[6];
    const float* bb_ih = (const float*)d_in[7];
    const float* bb_hh = (const float*)d_in[8];
    float* out = (float*)d_out;

    static int smem_set = 0;
    if (!smem_set) {
        cudaFuncSetAttribute(lstm_persist_kernel,
                             cudaFuncAttributeMaxDynamicSharedMemorySize,
                             SMEM_BYTES);
        smem_set = 1;
    }

    init_state_kernel<<<1, 32>>>();

    wfrag_prep_kernel<<<(2 * 64 * 8 * 64 * 32) / 256, 256>>>(Wf_hh, Wb_hh);

    dim3 ggrid(16384 / 128, 4096 / 128, 2);
    input_gemm_kernel<<<ggrid, 256>>>(x, Wf_ih, bf_ih, bf_hh,
                                      Wb_ih, bb_ih, bb_hh);

    const long long full = (long long)B_SZ * T_LEN * 2 * H_SZ
                         + 2LL * B_SZ * 2 * H_SZ;
    const int write_hc = ((long long)out_size >= full) ? 1 : 0;

    lstm_persist_kernel<<<NCTA, 256, SMEM_BYTES>>>(out, write_hc);
}

// round 8
// speedup vs baseline: 3.8199x; 1.3725x over previous
#include <cuda_runtime.h>
#include <cuda_fp16.h>

// Problem constants
#define T_LEN 512
#define B_SZ  32
#define D_IN  512
#define H_SZ  1024
#define G_SZ  4096   // 4*H
#define NCTA  128    // persistent grid: 64 gate-tiles x 2 dirs

// ---------------------------------------------------------------------------
// Scratch (allocation-free __device__ globals)
// g_xg   : [dir][s][b][g'] fp32 input contributions, g' = 4j+gate (i,f,g,o)
// g_WhhB : [dir][ct64][nt8][kk64][L32] uint2 {b0,b1} fp16x2 mma B frags of Whh
//          B[k][n] = W[(n&3)*H + (n>>2)][k], n = g', k = hidden j
// g_WihB : [dir][ntile512][kk32][L32] uint2 {b0,b1} fp16 B frags of Wih (k=D)
// g_xA   : [rt1024][kk32][L32][2] uint4 — x A-frags (hi/lo fp16 split),
//          physical-time row order r = t*32 + b, rt = r>>4
// g_hfrag: [buf2][dir2][mt2][kk64][lane32][reg4] uint2 {hi,lo} A frags of h
// g_bsum : [dir][g'] permuted bias sums
// g_arr/g_flag : distributed grid barrier (8 spread counters + broadcast flag)
// ---------------------------------------------------------------------------
__device__ float g_xg[(size_t)2 * T_LEN * B_SZ * G_SZ];     // 536 MB
__device__ uint2 g_WhhB[(size_t)2 * 64 * 8 * 64 * 32];      // 16.8 MB
__device__ uint2 g_WihB[(size_t)2 * 512 * 32 * 32];         // 8.4 MB
__device__ uint4 g_xA[(size_t)1024 * 32 * 32 * 2];          // 33.5 MB
__device__ uint2 g_hfrag[2 * 2 * 2 * 64 * 32 * 4];          // 1 MB
__device__ float g_bsum[2 * G_SZ];
__device__ unsigned g_arr[8 * 32];                          // stride-128B counters
__device__ unsigned g_flag;

// ---------------------------------------------------------------------------
__global__ void init_state_kernel() {
    int i = threadIdx.x;
    if (i < 8 * 32) g_arr[i] = 0u;
    if (i == 0) g_flag = 0u;
}

// ---------------------------------------------------------------------------
__device__ __forceinline__ unsigned pack_h2(float a, float b) {
    __half2 h;
    h.x = __float2half_rn(a); h.y = __float2half_rn(b);
    return *(unsigned*)&h;
}
__device__ __forceinline__ void split_h2(float a, float b,
                                         unsigned& hi, unsigned& lo) {
    __half ha = __float2half_rn(a), hb = __float2half_rn(b);
    hi = pack_h2(a, b);
    lo = pack_h2(a - __half2float(ha), b - __half2float(hb));
}

// ---------------------------------------------------------------------------
// W_hh -> fp16 mma B fragments. idx = ((((dir*64+ct)*8+nt)*64+kk)*32+L)
__global__ void whh_prep_kernel(const float* __restrict__ Wf,
                                const float* __restrict__ Wb) {
    unsigned idx = blockIdx.x * blockDim.x + threadIdx.x;
    if (idx >= (2u << 20)) return;
    const int L   = idx & 31;
    const int kk  = (idx >> 5) & 63;
    const int nt  = (idx >> 11) & 7;
    const int ct  = (idx >> 14) & 63;
    const int dir = idx >> 20;
    const float* __restrict__ W = dir ? Wb : Wf;

    const int gp = ((ct << 3) + nt) * 8 + (L >> 2);
    const float* row = W + (size_t)((gp & 3) * H_SZ + (gp >> 2)) * H_SZ;
    const int t2 = (L & 3) * 2;
    g_WhhB[idx] = make_uint2(pack_h2(row[kk * 16 + t2],     row[kk * 16 + t2 + 1]),
                             pack_h2(row[kk * 16 + t2 + 8], row[kk * 16 + t2 + 9]));
}

// W_ih -> fp16 mma B fragments. idx = (((dir*512+ntile)*32+kk)*32+L), k over D
__global__ void wih_prep_kernel(const float* __restrict__ Wf,
                                const float* __restrict__ Wb) {
    unsigned idx = blockIdx.x * blockDim.x + threadIdx.x;
    if (idx >= (1u << 20)) return;
    const int L   = idx & 31;
    const int kk  = (idx >> 5) & 31;
    const int ntl = (idx >> 10) & 511;
    const int dir = idx >> 19;
    const float* __restrict__ W = dir ? Wb : Wf;

    const int gp = (ntl << 3) + (L >> 2);
    const float* row = W + (size_t)((gp & 3) * H_SZ + (gp >> 2)) * D_IN;
    const int k0 = kk * 16 + (L & 3) * 2;
    g_WihB[idx] = make_uint2(pack_h2(row[k0],     row[k0 + 1]),
                             pack_h2(row[k0 + 8], row[k0 + 9]));
}

// Permuted bias sums: bsum[dir][g'] = bi[orig] + bh[orig]
__global__ void bsum_prep_kernel(const float* __restrict__ bfi,
                                 const float* __restrict__ bfh,
                                 const float* __restrict__ bbi,
                                 const float* __restrict__ bbh) {
    unsigned idx = blockIdx.x * blockDim.x + threadIdx.x;
    if (idx >= 2 * G_SZ) return;
    const int g = idx & (G_SZ - 1);
    const int dir = idx >> 12;
    const int orig = (g & 3) * H_SZ + (g >> 2);
    g_bsum[idx] = dir ? (bbi[orig] + bbh[orig]) : (bfi[orig] + bfh[orig]);
}

// x -> split-fp16 A fragments in physical-time row order.
// idx = ((rt*32 + kk)*32 + L); each thread writes 2 uint4s.
__global__ void xpack_kernel(const float* __restrict__ x) {
    unsigned idx = blockIdx.x * blockDim.x + threadIdx.x;
    if (idx >= (1u << 20)) return;
    const int L  = idx & 31;
    const int kk = (idx >> 5) & 31;
    const int rt = idx >> 10;
    const int r0 = rt * 16 + (L >> 2);
    const int r1 = r0 + 8;
    const int k0 = kk * 16 + (L & 3) * 2;
    const float* x0 = x + ((size_t)(r0 & 31) * T_LEN + (r0 >> 5)) * D_IN;
    const float* x1 = x + ((size_t)(r1 & 31) * T_LEN + (r1 >> 5)) * D_IN;
    uint4 p0, p1;
    split_h2(x0[k0],     x0[k0 + 1], p0.x, p0.y);
    split_h2(x1[k0],     x1[k0 + 1], p0.z, p0.w);
    split_h2(x0[k0 + 8], x0[k0 + 9], p1.x, p1.y);
    split_h2(x1[k0 + 8], x1[k0 + 9], p1.z, p1.w);
    g_xA[(size_t)idx * 2]     = p0;
    g_xA[(size_t)idx * 2 + 1] = p1;
}

// ---------------------------------------------------------------------------
__device__ __forceinline__ void mma_f16(float* c,
                                        unsigned a0, unsigned a1,
                                        unsigned a2, unsigned a3,
                                        unsigned b0, unsigned b1) {
    asm volatile(
        "mma.sync.aligned.m16n8k16.row.col.f32.f16.f16.f32 "
        "{%0,%1,%2,%3}, {%4,%5,%6,%7}, {%8,%9}, {%0,%1,%2,%3};"
        : "+f"(c[0]), "+f"(c[1]), "+f"(c[2]), "+f"(c[3])
        : "r"(a0), "r"(a1), "r"(a2), "r"(a3), "r"(b0), "r"(b1));
}

// ---------------------------------------------------------------------------
// Tensor-core input GEMM: xg = x @ Wih^T + bsum (gate-interleaved columns).
// CTA tile 128(M) x 128(N), K = 512 = 32 kk-steps, fp16 2-pass (x split, W
// single). B tile staged in 128 KB smem; A streamed from L2 with prefetch.
// Warp w = one m16 row-tile covering all 128 N cols (16 nt). Grid (128,32,2).
// ---------------------------------------------------------------------------
#define GEMM_SMEM (16 * 32 * 32 * 8)   // 131072

__global__ __launch_bounds__(256, 1)
void input_gemm_mma_kernel()
{
    extern __shared__ uint2 sB[];      // [ntl16][kk32][L32]
    const int dir = blockIdx.z;
    const int mc  = blockIdx.x;        // chain M-tile (128 rows = 4 s values)
    const int n0t = blockIdx.y * 16;   // base ntile (8 cols each)
    const int tid = threadIdx.x;
    const int w   = tid >> 5;
    const int L   = tid & 31;

    {   // stage B tile
        const uint2* src = g_WihB + ((size_t)dir * 512 + n0t) * (32 * 32);
        for (int i = tid; i < 16 * 32 * 32; i += 256) sB[i] = src[i];
    }
    __syncthreads();

    const int sw = mc * 4 + (w >> 1);             // chain step of this warp
    const int bh = w & 1;                          // batch half
    const int tp = dir ? (T_LEN - 1 - sw) : sw;    // physical time
    const uint4* __restrict__ aptr = g_xA + (size_t)(tp * 2 + bh) * 2048 + L * 2;

    float acc[16][4];
    #pragma unroll
    for (int nt = 0; nt < 16; nt++)
        #pragma unroll
        for (int i = 0; i < 4; i++) acc[nt][i] = 0.0f;

    uint4 A0 = aptr[0], A1 = aptr[1];
    for (int kk = 0; kk < 32; kk++) {
        const uint4 C0 = A0, C1 = A1;
        if (kk < 31) { A0 = aptr[(kk + 1) * 64]; A1 = aptr[(kk + 1) * 64 + 1]; }
        #pragma unroll
        for (int nt = 0; nt < 16; nt++) {
            const uint2 bb = sB[(nt * 32 + kk) * 32 + L];
            mma_f16(acc[nt], C0.x, C0.z, C1.x, C1.z, bb.x, bb.y);  // hi
            mma_f16(acc[nt], C0.y, C0.w, C1.y, C1.w, bb.x, bb.y);  // lo
        }
    }

    // epilogue: add bias, store to xg[dir][sw][b][g']
    const int b0 = bh * 16 + (L >> 2);
    const int b1 = b0 + 8;
    const int gb = n0t * 8 + (L & 3) * 2;
    float* xg0 = g_xg + (((size_t)dir * T_LEN + sw) * B_SZ + b0) * G_SZ;
    float* xg1 = g_xg + (((size_t)dir * T_LEN + sw) * B_SZ + b1) * G_SZ;
    const float* bs = g_bsum + dir * G_SZ;
    #pragma unroll
    for (int nt = 0; nt < 16; nt++) {
        const int g = gb + nt * 8;
        const float2 bias = *(const float2*)(bs + g);
        *(float2*)(xg0 + g) = make_float2(acc[nt][0] + bias.x, acc[nt][1] + bias.y);
        *(float2*)(xg1 + g) = make_float2(acc[nt][2] + bias.x, acc[nt][3] + bias.y);
    }
}

// ---------------------------------------------------------------------------
// Persistent bidirectional LSTM: all 512 steps in one kernel.
// Grid 128 = 64 gate-tiles x 2 dirs, 1 CTA/SM. 256 thr = 8 warps, warp w owns
// k-steps [8w,8w+8). W_hh fp16 fully resident in smem (zero W traffic/step);
// h split hi/lo fp16 A-frags double-buffered in global (__ldcg, L2-coherent);
// c in registers. 2-pass fp16 mma. Distributed grid barrier: 8 spread arrival
// counters + aggregator CTA + broadcast flag, bounded spins throughout.
// ---------------------------------------------------------------------------
#define WS_U2   16384                        // 8*64*32 uint2 (131072 B)
#define PS_OFF  (WS_U2 * 2)
#define PSW     2432                         // 32 rows * stride 76
#define SMEM_BYTES (WS_U2 * 8 + 8 * PSW * 4) // 208896

__global__ __launch_bounds__(256, 1)
void lstm_persist_kernel(float* __restrict__ out, int write_hc)
{
    extern __shared__ float sm[];
    uint2* ws = (uint2*)sm;
    float* ps = sm + PS_OFF;

    const int dir = blockIdx.x >> 6;
    const int ct  = blockIdx.x & 63;
    const int tid = threadIdx.x;
    const int w   = tid >> 5;
    const int L   = tid & 31;

    {   // load W_hh fp16 slice into smem (once)
        const uint2* src = g_WhhB + ((size_t)(dir * 64 + ct) << 14);
        for (int i = tid; i < WS_U2; i += 256) ws[i] = src[i];
    }

    int bb[2], ul[2];
    #pragma unroll
    for (int p = 0; p < 2; p++) {
        const int cid = tid + (p << 8);
        bb[p] = cid >> 4;
        ul[p] = cid & 15;
    }
    float creg[2] = {0.0f, 0.0f};

    const size_t OUT_HC0 = (size_t)B_SZ * T_LEN * 2 * H_SZ;
    const size_t OUT_HC1 = OUT_HC0 + (size_t)B_SZ * 2 * H_SZ;
    unsigned spin_limit = 50000000u;

    __syncthreads();

    for (int s = 0; s < T_LEN; s++) {
        const int buf  = s & 1;
        const int nbuf = buf ^ 1;

        const size_t xgbase = ((size_t)dir * T_LEN + s) * B_SZ * G_SZ;
        float4 xgv[2];
        #pragma unroll
        for (int p = 0; p < 2; p++)
            xgv[p] = __ldcg((const float4*)(g_xg + xgbase
                            + (size_t)bb[p] * G_SZ + (ct << 6) + (ul[p] << 2)));

        if (s > 0) {
            float acc[2][8][4];
            #pragma unroll
            for (int mt = 0; mt < 2; mt++)
                #pragma unroll
                for (int nt = 0; nt < 8; nt++)
                    #pragma unroll
                    for (int i = 0; i < 4; i++) acc[mt][nt][i] = 0.0f;

            const uint4* afb =
                (const uint4*)g_hfrag + ((size_t)(buf * 2 + dir) * 2) * (64 * 64);

            const int kk0 = w << 3;
            #pragma unroll 2
            for (int kk = kk0; kk < kk0 + 8; kk++) {
                uint4 A[2][2];
                #pragma unroll
                for (int mt = 0; mt < 2; mt++) {
                    const uint4* p = afb + ((size_t)mt * 64 + kk) * 64 + L * 2;
                    A[mt][0] = __ldcg(p);
                    A[mt][1] = __ldcg(p + 1);
                }
                #pragma unroll
                for (int nt = 0; nt < 8; nt++) {
                    const uint2 wh = ws[((nt << 6) + kk) * 32 + L];
                    #pragma unroll
                    for (int mt = 0; mt < 2; mt++) {
                        mma_f16(acc[mt][nt], A[mt][0].x, A[mt][0].z,
                                A[mt][1].x, A[mt][1].z, wh.x, wh.y);   // hi
                        mma_f16(acc[mt][nt], A[mt][0].y, A[mt][0].w,
                                A[mt][1].y, A[mt][1].w, wh.x, wh.y);   // lo
                    }
                }
            }

            float* psw = ps + w * PSW;
            const int r  = L >> 2;
            const int g2 = (L & 3) * 2;
            #pragma unroll
            for (int mt = 0; mt < 2; mt++)
                #pragma unroll
                for (int nt = 0; nt < 8; nt++) {
                    const int row = mt * 16 + r;
                    const int g   = nt * 8 + g2;
                    *(float2*)&psw[row * 76 + g] =
                        make_float2(acc[mt][nt][0], acc[mt][nt][1]);
                    *(float2*)&psw[(row + 8) * 76 + g] =
                        make_float2(acc[mt][nt][2], acc[mt][nt][3]);
                }
        }
        __syncthreads();

        const int tphys = dir ? (T_LEN - 1 - s) : s;
        #pragma unroll
        for (int p = 0; p < 2; p++) {
            const int b = bb[p];
            const int u = ul[p];
            const int j = (ct << 4) + u;

            float4 v = make_float4(0.f, 0.f, 0.f, 0.f);
            if (s > 0) {
                #pragma unroll
                for (int ww = 0; ww < 8; ww++) {
                    const float4 q = *(const float4*)&ps[ww * PSW + b * 76 + u * 4];
                    v.x += q.x; v.y += q.y; v.z += q.z; v.w += q.w;
                }
            }

            float iv = v.x + xgv[p].x;
            float fv = v.y + xgv[p].y;
            float gv = v.z + xgv[p].z;
            float ov = v.w + xgv[p].w;
            iv = 1.0f / (1.0f + __expf(-iv));
            fv = 1.0f / (1.0f + __expf(-fv));
            ov = 1.0f / (1.0f + __expf(-ov));
            gv = tanhf(gv);
            const float cc = fv * creg[p] + iv * gv;
            creg[p] = cc;
            const float h = ov * tanhf(cc);

            out[((size_t)b * T_LEN + tphys) * (2 * H_SZ) + (size_t)dir * H_SZ + j] = h;
            if (write_hc && s == T_LEN - 1) {
                out[OUT_HC0 + ((size_t)b * 2 + dir) * H_SZ + j] = h;
                out[OUT_HC1 + ((size_t)b * 2 + dir) * H_SZ + j] = cc;
            }

            const float hn = __shfl_down_sync(0xffffffffu, h, 1);
            if ((u & 1) == 0) {
                unsigned hi, lo;
                split_h2(h, hn, hi, lo);
                const int mt    = b >> 4;
                const int rowin = b & 15;
                const int reg   = (rowin >> 3) + ((u >> 3) << 1);
                const int lane2 = (rowin & 7) * 4 + ((u & 7) >> 1);
                uint2* dst = g_hfrag
                    + (((size_t)(nbuf * 2 + dir) * 2 + mt) * 64 + ct) * 128
                    + lane2 * 4 + reg;
                *dst = make_uint2(hi, lo);
            }
        }

        // distributed grid barrier (bounded spins — degrades, never hangs)
        __syncthreads();
        if (tid == 0) {
            __threadfence();
            unsigned* ctr = &g_arr[(blockIdx.x & 7) * 32];
            asm volatile("red.release.gpu.global.add.u32 [%0], 1;"
                         :: "l"(ctr) : "memory");
            if (blockIdx.x == 0) {
                const unsigned tgt = (unsigned)(s + 1) * 16;
                unsigned it = 0;
                for (;;) {
                    unsigned done = 1;
                    #pragma unroll
                    for (int q = 0; q < 8; q++) {
                        unsigned vv;
                        asm volatile("ld.acquire.gpu.global.u32 %0, [%1];"
                                     : "=r"(vv) : "l"(&g_arr[q * 32]) : "memory");
                        done &= (unsigned)(vv >= tgt);
                    }
                    if (done) break;
                    if (++it >= spin_limit) { spin_limit = 0; break; }
                }
                asm volatile("st.release.gpu.global.u32 [%0], %1;"
                             :: "l"(&g_flag), "r"((unsigned)(s + 1)) : "memory");
            }
            unsigned vv, it2 = 0;
            for (;;) {
                asm volatile("ld.acquire.gpu.global.u32 %0, [%1];"
                             : "=r"(vv) : "l"(&g_flag) : "memory");
                if (vv >= (unsigned)(s + 1)) break;
                if (++it2 >= spin_limit) { spin_limit = 0; break; }
            }
            __threadfence();
        }
        __syncthreads();
    }
}

// ---------------------------------------------------------------------------
extern "C" void kernel_launch(void* const* d_in, const int* in_sizes, int n_in,
                              void* d_out, int out_size)
{
    const float* x     = (const float*)d_in[0];
    const float* Wf_ih = (const float*)d_in[1];
    const float* Wf_hh = (const float*)d_in[2];
    const float* bf_ih = (const float*)d_in[3];
    const float* bf_hh = (const float*)d_in[4];
    const float* Wb_ih = (const float*)d_in[5];
    const float* Wb_hh = (const float*)d_in[6];
    const float* bb_ih = (const float*)d_in[7];
    const float* bb_hh = (const float*)d_in[8];
    float* out = (float*)d_out;

    static int smem_set = 0;
    if (!smem_set) {
        cudaFuncSetAttribute(lstm_persist_kernel,
                             cudaFuncAttributeMaxDynamicSharedMemorySize,
                             SMEM_BYTES);
        cudaFuncSetAttribute(input_gemm_mma_kernel,
                             cudaFuncAttributeMaxDynamicSharedMemorySize,
                             GEMM_SMEM);
        smem_set = 1;
    }

    init_state_kernel<<<1, 256>>>();

    whh_prep_kernel<<<(2 * 64 * 8 * 64 * 32) / 256, 256>>>(Wf_hh, Wb_hh);
    wih_prep_kernel<<<(2 * 512 * 32 * 32) / 256, 256>>>(Wf_ih, Wb_ih);
    bsum_prep_kernel<<<(2 * G_SZ) / 256, 256>>>(bf_ih, bf_hh, bb_ih, bb_hh);
    xpack_kernel<<<(1024 * 32 * 32) / 256, 256>>>(x);

    input_gemm_mma_kernel<<<dim3(128, 32, 2), 256, GEMM_SMEM>>>();

    const long long full = (long long)B_SZ * T_LEN * 2 * H_SZ
                         + 2LL * B_SZ * 2 * H_SZ;
    const int write_hc = ((long long)out_size >= full) ? 1 : 0;

    lstm_persist_kernel<<<NCTA, 256, SMEM_BYTES>>>(out, write_hc);
}

// round 9
// speedup vs baseline: 4.4872x; 1.1747x over previous
#include <cuda_runtime.h>
#include <cuda_fp16.h>

// Problem constants
#define T_LEN 512
#define B_SZ  32
#define D_IN  512
#define H_SZ  1024
#define G_SZ  4096   // 4*H
#define NCTA  128    // persistent grid: 64 gate-tiles x 2 dirs

// ---------------------------------------------------------------------------
// Scratch (allocation-free __device__ globals)
// g_xg   : [dir][s][b][g'] fp32 input contributions, g' = 4j+gate (i,f,g,o)
// g_WhhB : [dir][ct64][nt8][kk64][L32] uint2 {b0,b1} fp16x2 mma B frags of Whh
// g_WihB : [dir][ntile512][kk32][L32] uint2 {b0,b1} fp16 B frags of Wih (k=D)
// g_xA   : [rt1024][kk32][L32][2] uint4 — x A-frags (hi/lo fp16 split)
// g_hfrag: [buf2][dir2][mt2][kk64][lane32][reg4] uint2 {hi,lo} A frags of h
// g_bsum : [dir][g'] permuted bias sums
// g_arr  : flat per-direction grid barrier: [dir][q4] spread counters
// ---------------------------------------------------------------------------
__device__ float g_xg[(size_t)2 * T_LEN * B_SZ * G_SZ];     // 536 MB
__device__ uint2 g_WhhB[(size_t)2 * 64 * 8 * 64 * 32];      // 16.8 MB
__device__ uint2 g_WihB[(size_t)2 * 512 * 32 * 32];         // 8.4 MB
__device__ uint4 g_xA[(size_t)1024 * 32 * 32 * 2];          // 33.5 MB
__device__ uint2 g_hfrag[2 * 2 * 2 * 64 * 32 * 4];          // 1 MB
__device__ float g_bsum[2 * G_SZ];
__device__ unsigned g_arr[2 * 4 * 32];                      // 128B-spread counters

// ---------------------------------------------------------------------------
__global__ void init_state_kernel() {
    int i = threadIdx.x;
    if (i < 2 * 4 * 32) g_arr[i] = 0u;
}

// ---------------------------------------------------------------------------
__device__ __forceinline__ unsigned pack_h2(float a, float b) {
    __half2 h;
    h.x = __float2half_rn(a); h.y = __float2half_rn(b);
    return *(unsigned*)&h;
}
__device__ __forceinline__ void split_h2(float a, float b,
                                         unsigned& hi, unsigned& lo) {
    __half ha = __float2half_rn(a), hb = __float2half_rn(b);
    hi = pack_h2(a, b);
    lo = pack_h2(a - __half2float(ha), b - __half2float(hb));
}
__device__ __forceinline__ float sigm(float x) {
    return 1.0f / (1.0f + __expf(-x));
}
__device__ __forceinline__ float ftanh(float x) {
    return __fmaf_rn(2.0f, sigm(2.0f * x), -1.0f);
}

// ---------------------------------------------------------------------------
// W_hh -> fp16 mma B fragments. idx = ((((dir*64+ct)*8+nt)*64+kk)*32+L)
__global__ void whh_prep_kernel(const float* __restrict__ Wf,
                                const float* __restrict__ Wb) {
    unsigned idx = blockIdx.x * blockDim.x + threadIdx.x;
    if (idx >= (2u << 20)) return;
    const int L   = idx & 31;
    const int kk  = (idx >> 5) & 63;
    const int nt  = (idx >> 11) & 7;
    const int ct  = (idx >> 14) & 63;
    const int dir = idx >> 20;
    const float* __restrict__ W = dir ? Wb : Wf;

    const int gp = ((ct << 3) + nt) * 8 + (L >> 2);
    const float* row = W + (size_t)((gp & 3) * H_SZ + (gp >> 2)) * H_SZ;
    const int t2 = (L & 3) * 2;
    g_WhhB[idx] = make_uint2(pack_h2(row[kk * 16 + t2],     row[kk * 16 + t2 + 1]),
                             pack_h2(row[kk * 16 + t2 + 8], row[kk * 16 + t2 + 9]));
}

// W_ih -> fp16 mma B fragments. idx = (((dir*512+ntile)*32+kk)*32+L), k over D
__global__ void wih_prep_kernel(const float* __restrict__ Wf,
                                const float* __restrict__ Wb) {
    unsigned idx = blockIdx.x * blockDim.x + threadIdx.x;
    if (idx >= (1u << 20)) return;
    const int L   = idx & 31;
    const int kk  = (idx >> 5) & 31;
    const int ntl = (idx >> 10) & 511;
    const int dir = idx >> 19;
    const float* __restrict__ W = dir ? Wb : Wf;

    const int gp = (ntl << 3) + (L >> 2);
    const float* row = W + (size_t)((gp & 3) * H_SZ + (gp >> 2)) * D_IN;
    const int k0 = kk * 16 + (L & 3) * 2;
    g_WihB[idx] = make_uint2(pack_h2(row[k0],     row[k0 + 1]),
                             pack_h2(row[k0 + 8], row[k0 + 9]));
}

// Permuted bias sums: bsum[dir][g'] = bi[orig] + bh[orig]
__global__ void bsum_prep_kernel(const float* __restrict__ bfi,
                                 const float* __restrict__ bfh,
                                 const float* __restrict__ bbi,
                                 const float* __restrict__ bbh) {
    unsigned idx = blockIdx.x * blockDim.x + threadIdx.x;
    if (idx >= 2 * G_SZ) return;
    const int g = idx & (G_SZ - 1);
    const int dir = idx >> 12;
    const int orig = (g & 3) * H_SZ + (g >> 2);
    g_bsum[idx] = dir ? (bbi[orig] + bbh[orig]) : (bfi[orig] + bfh[orig]);
}

// x -> split-fp16 A fragments in physical-time row order.
__global__ void xpack_kernel(const float* __restrict__ x) {
    unsigned idx = blockIdx.x * blockDim.x + threadIdx.x;
    if (idx >= (1u << 20)) return;
    const int L  = idx & 31;
    const int kk = (idx >> 5) & 31;
    const int rt = idx >> 10;
    const int r0 = rt * 16 + (L >> 2);
    const int r1 = r0 + 8;
    const int k0 = kk * 16 + (L & 3) * 2;
    const float* x0 = x + ((size_t)(r0 & 31) * T_LEN + (r0 >> 5)) * D_IN;
    const float* x1 = x + ((size_t)(r1 & 31) * T_LEN + (r1 >> 5)) * D_IN;
    uint4 p0, p1;
    split_h2(x0[k0],     x0[k0 + 1], p0.x, p0.y);
    split_h2(x1[k0],     x1[k0 + 1], p0.z, p0.w);
    split_h2(x0[k0 + 8], x0[k0 + 9], p1.x, p1.y);
    split_h2(x1[k0 + 8], x1[k0 + 9], p1.z, p1.w);
    g_xA[(size_t)idx * 2]     = p0;
    g_xA[(size_t)idx * 2 + 1] = p1;
}

// ---------------------------------------------------------------------------
__device__ __forceinline__ void mma_f16(float* c,
                                        unsigned a0, unsigned a1,
                                        unsigned a2, unsigned a3,
                                        unsigned b0, unsigned b1) {
    asm volatile(
        "mma.sync.aligned.m16n8k16.row.col.f32.f16.f16.f32 "
        "{%0,%1,%2,%3}, {%4,%5,%6,%7}, {%8,%9}, {%0,%1,%2,%3};"
        : "+f"(c[0]), "+f"(c[1]), "+f"(c[2]), "+f"(c[3])
        : "r"(a0), "r"(a1), "r"(a2), "r"(a3), "r"(b0), "r"(b1));
}

// ---------------------------------------------------------------------------
// Tensor-core input GEMM (unchanged from R8).
// ---------------------------------------------------------------------------
#define GEMM_SMEM (16 * 32 * 32 * 8)   // 131072

__global__ __launch_bounds__(256, 1)
void input_gemm_mma_kernel()
{
    extern __shared__ uint2 sB[];      // [ntl16][kk32][L32]
    const int dir = blockIdx.z;
    const int mc  = blockIdx.x;
    const int n0t = blockIdx.y * 16;
    const int tid = threadIdx.x;
    const int w   = tid >> 5;
    const int L   = tid & 31;

    {
        const uint2* src = g_WihB + ((size_t)dir * 512 + n0t) * (32 * 32);
        for (int i = tid; i < 16 * 32 * 32; i += 256) sB[i] = src[i];
    }
    __syncthreads();

    const int sw = mc * 4 + (w >> 1);
    const int bh = w & 1;
    const int tp = dir ? (T_LEN - 1 - sw) : sw;
    const uint4* __restrict__ aptr = g_xA + (size_t)(tp * 2 + bh) * 2048 + L * 2;

    float acc[16][4];
    #pragma unroll
    for (int nt = 0; nt < 16; nt++)
        #pragma unroll
        for (int i = 0; i < 4; i++) acc[nt][i] = 0.0f;

    uint4 A0 = aptr[0], A1 = aptr[1];
    for (int kk = 0; kk < 32; kk++) {
        const uint4 C0 = A0, C1 = A1;
        if (kk < 31) { A0 = aptr[(kk + 1) * 64]; A1 = aptr[(kk + 1) * 64 + 1]; }
        #pragma unroll
        for (int nt = 0; nt < 16; nt++) {
            const uint2 bb = sB[(nt * 32 + kk) * 32 + L];
            mma_f16(acc[nt], C0.x, C0.z, C1.x, C1.z, bb.x, bb.y);  // hi
            mma_f16(acc[nt], C0.y, C0.w, C1.y, C1.w, bb.x, bb.y);  // lo
        }
    }

    const int b0 = bh * 16 + (L >> 2);
    const int b1 = b0 + 8;
    const int gb = n0t * 8 + (L & 3) * 2;
    float* xg0 = g_xg + (((size_t)dir * T_LEN + sw) * B_SZ + b0) * G_SZ;
    float* xg1 = g_xg + (((size_t)dir * T_LEN + sw) * B_SZ + b1) * G_SZ;
    const float* bs = g_bsum + dir * G_SZ;
    #pragma unroll
    for (int nt = 0; nt < 16; nt++) {
        const int g = gb + nt * 8;
        const float2 bias = *(const float2*)(bs + g);
        *(float2*)(xg0 + g) = make_float2(acc[nt][0] + bias.x, acc[nt][1] + bias.y);
        *(float2*)(xg1 + g) = make_float2(acc[nt][2] + bias.x, acc[nt][3] + bias.y);
    }
}

// ---------------------------------------------------------------------------
// Persistent bidirectional LSTM, v3.
// Changes vs R8: depth-2 software pipeline on the A-fragment __ldcg loads,
// flat per-direction grid barrier (one L2 round trip, dirs decoupled),
// __expf-based sigmoid/tanh epilogue (no slow tanhf path).
// ---------------------------------------------------------------------------
#define WS_U2   16384                        // 8*64*32 uint2 (131072 B)
#define PS_OFF  (WS_U2 * 2)
#define PSW     2432                         // 32 rows * stride 76
#define SMEM_BYTES (WS_U2 * 8 + 8 * PSW * 4) // 208896

__global__ __launch_bounds__(256, 1)
void lstm_persist_kernel(float* __restrict__ out, int write_hc)
{
    extern __shared__ float sm[];
    uint2* ws = (uint2*)sm;
    float* ps = sm + PS_OFF;

    const int dir = blockIdx.x >> 6;
    const int ct  = blockIdx.x & 63;
    const int tid = threadIdx.x;
    const int w   = tid >> 5;
    const int L   = tid & 31;

    {   // load W_hh fp16 slice into smem (once)
        const uint2* src = g_WhhB + ((size_t)(dir * 64 + ct) << 14);
        for (int i = tid; i < WS_U2; i += 256) ws[i] = src[i];
    }

    int bb[2], ul[2];
    #pragma unroll
    for (int p = 0; p < 2; p++) {
        const int cid = tid + (p << 8);
        bb[p] = cid >> 4;
        ul[p] = cid & 15;
    }
    float creg[2] = {0.0f, 0.0f};

    const size_t OUT_HC0 = (size_t)B_SZ * T_LEN * 2 * H_SZ;
    const size_t OUT_HC1 = OUT_HC0 + (size_t)B_SZ * 2 * H_SZ;
    unsigned spin_limit = 50000000u;

    __syncthreads();

    for (int s = 0; s < T_LEN; s++) {
        const int buf  = s & 1;
        const int nbuf = buf ^ 1;

        const size_t xgbase = ((size_t)dir * T_LEN + s) * B_SZ * G_SZ;
        float4 xgv[2];
        #pragma unroll
        for (int p = 0; p < 2; p++)
            xgv[p] = __ldcg((const float4*)(g_xg + xgbase
                            + (size_t)bb[p] * G_SZ + (ct << 6) + (ul[p] << 2)));

        if (s > 0) {
            float acc[2][8][4];
            #pragma unroll
            for (int mt = 0; mt < 2; mt++)
                #pragma unroll
                for (int nt = 0; nt < 8; nt++)
                    #pragma unroll
                    for (int i = 0; i < 4; i++) acc[mt][nt][i] = 0.0f;

            const uint4* afb =
                (const uint4*)g_hfrag + ((size_t)(buf * 2 + dir) * 2) * (64 * 64);
            const int kk0 = w << 3;

            // depth-2 pipelined A-fragment loads
            uint4 A[2][2][2];   // [stage][mt][half]
            #pragma unroll
            for (int st = 0; st < 2; st++)
                #pragma unroll
                for (int mt = 0; mt < 2; mt++) {
                    const uint4* p = afb + ((size_t)mt * 64 + kk0 + st) * 64 + L * 2;
                    A[st][mt][0] = __ldcg(p);
                    A[st][mt][1] = __ldcg(p + 1);
                }

            #pragma unroll
            for (int i = 0; i < 8; i++) {
                const int st = i & 1;
                const int kk = kk0 + i;
                #pragma unroll
                for (int nt = 0; nt < 8; nt++) {
                    const uint2 wh = ws[((nt << 6) + kk) * 32 + L];
                    #pragma unroll
                    for (int mt = 0; mt < 2; mt++) {
                        mma_f16(acc[mt][nt], A[st][mt][0].x, A[st][mt][0].z,
                                A[st][mt][1].x, A[st][mt][1].z, wh.x, wh.y);  // hi
                        mma_f16(acc[mt][nt], A[st][mt][0].y, A[st][mt][0].w,
                                A[st][mt][1].y, A[st][mt][1].w, wh.x, wh.y);  // lo
                    }
                }
                if (i + 2 < 8) {
                    #pragma unroll
                    for (int mt = 0; mt < 2; mt++) {
                        const uint4* p = afb + ((size_t)mt * 64 + kk0 + i + 2) * 64
                                         + L * 2;
                        A[st][mt][0] = __ldcg(p);
                        A[st][mt][1] = __ldcg(p + 1);
                    }
                }
            }

            float* psw = ps + w * PSW;
            const int r  = L >> 2;
            const int g2 = (L & 3) * 2;
            #pragma unroll
            for (int mt = 0; mt < 2; mt++)
                #pragma unroll
                for (int nt = 0; nt < 8; nt++) {
                    const int row = mt * 16 + r;
                    const int g   = nt * 8 + g2;
                    *(float2*)&psw[row * 76 + g] =
                        make_float2(acc[mt][nt][0], acc[mt][nt][1]);
                    *(float2*)&psw[(row + 8) * 76 + g] =
                        make_float2(acc[mt][nt][2], acc[mt][nt][3]);
                }
        }
        __syncthreads();

        const int tphys = dir ? (T_LEN - 1 - s) : s;
        #pragma unroll
        for (int p = 0; p < 2; p++) {
            const int b = bb[p];
            const int u = ul[p];
            const int j = (ct << 4) + u;

            float4 v = make_float4(0.f, 0.f, 0.f, 0.f);
            if (s > 0) {
                #pragma unroll
                for (int ww = 0; ww < 8; ww++) {
                    const float4 q = *(const float4*)&ps[ww * PSW + b * 76 + u * 4];
                    v.x += q.x; v.y += q.y; v.z += q.z; v.w += q.w;
                }
            }

            const float iv = sigm(v.x + xgv[p].x);
            const float fv = sigm(v.y + xgv[p].y);
            const float gv = ftanh(v.z + xgv[p].z);
            const float ov = sigm(v.w + xgv[p].w);
            const float cc = fv * creg[p] + iv * gv;
            creg[p] = cc;
            const float h = ov * ftanh(cc);

            out[((size_t)b * T_LEN + tphys) * (2 * H_SZ) + (size_t)dir * H_SZ + j] = h;
            if (write_hc && s == T_LEN - 1) {
                out[OUT_HC0 + ((size_t)b * 2 + dir) * H_SZ + j] = h;
                out[OUT_HC1 + ((size_t)b * 2 + dir) * H_SZ + j] = cc;
            }

            const float hn = __shfl_down_sync(0xffffffffu, h, 1);
            if ((u & 1) == 0) {
                unsigned hi, lo;
                split_h2(h, hn, hi, lo);
                const int mt    = b >> 4;
                const int rowin = b & 15;
                const int reg   = (rowin >> 3) + ((u >> 3) << 1);
                const int lane2 = (rowin & 7) * 4 + ((u & 7) >> 1);
                uint2* dst = g_hfrag
                    + (((size_t)(nbuf * 2 + dir) * 2 + mt) * 64 + ct) * 128
                    + lane2 * 4 + reg;
                *dst = make_uint2(hi, lo);
            }
        }

        // flat per-direction grid barrier (64 CTAs, 4 spread counters).
        // release-RED orders prior h stores; acquire-LD orders next reads;
        // __syncthreads propagates tid0's visibility CTA-wide. Bounded spin.
        __syncthreads();
        if (tid == 0) {
            unsigned* ctr = &g_arr[(dir * 4 + (ct & 3)) * 32];
            asm volatile("red.release.gpu.global.add.u32 [%0], 1;"
                         :: "l"(ctr) : "memory");
            const unsigned tgt = (unsigned)(s + 1) * 16;
            unsigned it = 0;
            for (;;) {
                unsigned done = 1;
                #pragma unroll
                for (int q = 0; q < 4; q++) {
                    unsigned vv;
                    asm volatile("ld.acquire.gpu.global.u32 %0, [%1];"
                                 : "=r"(vv) : "l"(&g_arr[(dir * 4 + q) * 32])
                                 : "memory");
                    done &= (unsigned)(vv >= tgt);
                }
                if (done) break;
                if (++it >= spin_limit) { spin_limit = 0; break; }
            }
        }
        __syncthreads();
    }
}

// ---------------------------------------------------------------------------
extern "C" void kernel_launch(void* const* d_in, const int* in_sizes, int n_in,
                              void* d_out, int out_size)
{
    const float* x     = (const float*)d_in[0];
    const float* Wf_ih = (const float*)d_in[1];
    const float* Wf_hh = (const float*)d_in[2];
    const float* bf_ih = (const float*)d_in[3];
    const float* bf_hh = (const float*)d_in[4];
    const float* Wb_ih = (const float*)d_in[5];
    const float* Wb_hh = (const float*)d_in[6];
    const float* bb_ih = (const float*)d_in[7];
    const float* bb_hh = (const float*)d_in[8];
    float* out = (float*)d_out;

    static int smem_set = 0;
    if (!smem_set) {
        cudaFuncSetAttribute(lstm_persist_kernel,
                             cudaFuncAttributeMaxDynamicSharedMemorySize,
                             SMEM_BYTES);
        cudaFuncSetAttribute(input_gemm_mma_kernel,
                             cudaFuncAttributeMaxDynamicSharedMemorySize,
                             GEMM_SMEM);
        smem_set = 1;
    }

    init_state_kernel<<<1, 256>>>();

    whh_prep_kernel<<<(2 * 64 * 8 * 64 * 32) / 256, 256>>>(Wf_hh, Wb_hh);
    wih_prep_kernel<<<(2 * 512 * 32 * 32) / 256, 256>>>(Wf_ih, Wb_ih);
    bsum_prep_kernel<<<(2 * G_SZ) / 256, 256>>>(bf_ih, bf_hh, bb_ih, bb_hh);
    xpack_kernel<<<(1024 * 32 * 32) / 256, 256>>>(x);

    input_gemm_mma_kernel<<<dim3(128, 32, 2), 256, GEMM_SMEM>>>();

    const long long full = (long long)B_SZ * T_LEN * 2 * H_SZ
                         + 2LL * B_SZ * 2 * H_SZ;
    const int write_hc = ((long long)out_size >= full) ? 1 : 0;

    lstm_persist_kernel<<<NCTA, 256, SMEM_BYTES>>>(out, write_hc);
}

// round 10
// speedup vs baseline: 6.0949x; 1.3583x over previous
#include <cuda_runtime.h>
#include <cuda_fp16.h>

// Problem constants
#define T_LEN 512
#define B_SZ  32
#define D_IN  512
#define H_SZ  1024
#define G_SZ  4096   // 4*H
#define NCTA  128    // persistent grid: 64 gate-tiles x 2 dirs

// ---------------------------------------------------------------------------
// Scratch (allocation-free __device__ globals)
// g_xg    : [dir][s][b][g'] fp32 input contributions, g' = 4j+gate (i,f,g,o)
// g_WhhB  : [dir][ct64][nt8][kk64][L32] uint2 {b0,b1} fp16 mma B frags of Whh
// g_WihB  : [dir][ntile512][kk32][L32] uint2 {b0,b1} fp16 B frags of Wih
// g_xAH   : [rt1024][kk32][L32] uint4 {a0,a1,a2,a3} fp16 A frags of x (hi only)
// g_hfragH: [buf2][dir2][mt2][kk64][lane32][reg4] unsigned — fp16 A frags of h
// g_bsum  : [dir][g'] permuted bias sums
// g_arr   : flat per-direction grid barrier: [dir][q4] spread counters
// ---------------------------------------------------------------------------
__device__ float g_xg[(size_t)2 * T_LEN * B_SZ * G_SZ];     // 536 MB
__device__ uint2 g_WhhB[(size_t)2 * 64 * 8 * 64 * 32];      // 16.8 MB
__device__ uint2 g_WihB[(size_t)2 * 512 * 32 * 32];         // 8.4 MB
__device__ uint4 g_xAH[(size_t)1024 * 32 * 32];             // 16.8 MB
__device__ unsigned g_hfragH[2 * 2 * 2 * 64 * 32 * 4];      // 0.5 MB
__device__ float g_bsum[2 * G_SZ];
__device__ unsigned g_arr[2 * 4 * 32];                      // 128B-spread counters

// ---------------------------------------------------------------------------
__global__ void init_state_kernel() {
    int i = threadIdx.x;
    if (i < 2 * 4 * 32) g_arr[i] = 0u;
}

// ---------------------------------------------------------------------------
__device__ __forceinline__ unsigned pack_h2(float a, float b) {
    __half2 h;
    h.x = __float2half_rn(a); h.y = __float2half_rn(b);
    return *(unsigned*)&h;
}
__device__ __forceinline__ float sigm(float x) {
    return 1.0f / (1.0f + __expf(-x));
}
__device__ __forceinline__ float ftanh(float x) {
    return __fmaf_rn(2.0f, sigm(2.0f * x), -1.0f);
}

// ---------------------------------------------------------------------------
// W_hh -> fp16 mma B fragments. idx = ((((dir*64+ct)*8+nt)*64+kk)*32+L)
__global__ void whh_prep_kernel(const float* __restrict__ Wf,
                                const float* __restrict__ Wb) {
    unsigned idx = blockIdx.x * blockDim.x + threadIdx.x;
    if (idx >= (2u << 20)) return;
    const int L   = idx & 31;
    const int kk  = (idx >> 5) & 63;
    const int nt  = (idx >> 11) & 7;
    const int ct  = (idx >> 14) & 63;
    const int dir = idx >> 20;
    const float* __restrict__ W = dir ? Wb : Wf;

    const int gp = ((ct << 3) + nt) * 8 + (L >> 2);
    const float* row = W + (size_t)((gp & 3) * H_SZ + (gp >> 2)) * H_SZ;
    const int t2 = (L & 3) * 2;
    g_WhhB[idx] = make_uint2(pack_h2(row[kk * 16 + t2],     row[kk * 16 + t2 + 1]),
                             pack_h2(row[kk * 16 + t2 + 8], row[kk * 16 + t2 + 9]));
}

// W_ih -> fp16 mma B fragments. idx = (((dir*512+ntile)*32+kk)*32+L), k over D
__global__ void wih_prep_kernel(const float* __restrict__ Wf,
                                const float* __restrict__ Wb) {
    unsigned idx = blockIdx.x * blockDim.x + threadIdx.x;
    if (idx >= (1u << 20)) return;
    const int L   = idx & 31;
    const int kk  = (idx >> 5) & 31;
    const int ntl = (idx >> 10) & 511;
    const int dir = idx >> 19;
    const float* __restrict__ W = dir ? Wb : Wf;

    const int gp = (ntl << 3) + (L >> 2);
    const float* row = W + (size_t)((gp & 3) * H_SZ + (gp >> 2)) * D_IN;
    const int k0 = kk * 16 + (L & 3) * 2;
    g_WihB[idx] = make_uint2(pack_h2(row[k0],     row[k0 + 1]),
                             pack_h2(row[k0 + 8], row[k0 + 9]));
}

// Permuted bias sums: bsum[dir][g'] = bi[orig] + bh[orig]
__global__ void bsum_prep_kernel(const float* __restrict__ bfi,
                                 const float* __restrict__ bfh,
                                 const float* __restrict__ bbi,
                                 const float* __restrict__ bbh) {
    unsigned idx = blockIdx.x * blockDim.x + threadIdx.x;
    if (idx >= 2 * G_SZ) return;
    const int g = idx & (G_SZ - 1);
    const int dir = idx >> 12;
    const int orig = (g & 3) * H_SZ + (g >> 2);
    g_bsum[idx] = dir ? (bbi[orig] + bbh[orig]) : (bfi[orig] + bfh[orig]);
}

// x -> fp16 A fragments (hi only) in physical-time row order.
__global__ void xpack_kernel(const float* __restrict__ x) {
    unsigned idx = blockIdx.x * blockDim.x + threadIdx.x;
    if (idx >= (1u << 20)) return;
    const int L  = idx & 31;
    const int kk = (idx >> 5) & 31;
    const int rt = idx >> 10;
    const int r0 = rt * 16 + (L >> 2);
    const int r1 = r0 + 8;
    const int k0 = kk * 16 + (L & 3) * 2;
    const float* x0 = x + ((size_t)(r0 & 31) * T_LEN + (r0 >> 5)) * D_IN;
    const float* x1 = x + ((size_t)(r1 & 31) * T_LEN + (r1 >> 5)) * D_IN;
    uint4 p;
    p.x = pack_h2(x0[k0],     x0[k0 + 1]);     // a0
    p.y = pack_h2(x1[k0],     x1[k0 + 1]);     // a1
    p.z = pack_h2(x0[k0 + 8], x0[k0 + 9]);     // a2
    p.w = pack_h2(x1[k0 + 8], x1[k0 + 9]);     // a3
    g_xAH[idx] = p;
}

// ---------------------------------------------------------------------------
__device__ __forceinline__ void mma_f16(float* c,
                                        unsigned a0, unsigned a1,
                                        unsigned a2, unsigned a3,
                                        unsigned b0, unsigned b1) {
    asm volatile(
        "mma.sync.aligned.m16n8k16.row.col.f32.f16.f16.f32 "
        "{%0,%1,%2,%3}, {%4,%5,%6,%7}, {%8,%9}, {%0,%1,%2,%3};"
        : "+f"(c[0]), "+f"(c[1]), "+f"(c[2]), "+f"(c[3])
        : "r"(a0), "r"(a1), "r"(a2), "r"(a3), "r"(b0), "r"(b1));
}

// ---------------------------------------------------------------------------
// Tensor-core input GEMM, single-pass fp16.
// ---------------------------------------------------------------------------
#define GEMM_SMEM (16 * 32 * 32 * 8)   // 131072

__global__ __launch_bounds__(256, 1)
void input_gemm_mma_kernel()
{
    extern __shared__ uint2 sB[];      // [ntl16][kk32][L32]
    const int dir = blockIdx.z;
    const int mc  = blockIdx.x;
    const int n0t = blockIdx.y * 16;
    const int tid = threadIdx.x;
    const int w   = tid >> 5;
    const int L   = tid & 31;

    {
        const uint2* src = g_WihB + ((size_t)dir * 512 + n0t) * (32 * 32);
        for (int i = tid; i < 16 * 32 * 32; i += 256) sB[i] = src[i];
    }
    __syncthreads();

    const int sw = mc * 4 + (w >> 1);
    const int bh = w & 1;
    const int tp = dir ? (T_LEN - 1 - sw) : sw;
    const uint4* __restrict__ aptr = g_xAH + (size_t)(tp * 2 + bh) * 1024 + L;

    float acc[16][4];
    #pragma unroll
    for (int nt = 0; nt < 16; nt++)
        #pragma unroll
        for (int i = 0; i < 4; i++) acc[nt][i] = 0.0f;

    uint4 A = aptr[0];
    for (int kk = 0; kk < 32; kk++) {
        const uint4 C = A;
        if (kk < 31) A = aptr[(kk + 1) * 32];
        #pragma unroll
        for (int nt = 0; nt < 16; nt++) {
            const uint2 bb = sB[(nt * 32 + kk) * 32 + L];
            mma_f16(acc[nt], C.x, C.y, C.z, C.w, bb.x, bb.y);
        }
    }

    const int b0 = bh * 16 + (L >> 2);
    const int b1 = b0 + 8;
    const int gb = n0t * 8 + (L & 3) * 2;
    float* xg0 = g_xg + (((size_t)dir * T_LEN + sw) * B_SZ + b0) * G_SZ;
    float* xg1 = g_xg + (((size_t)dir * T_LEN + sw) * B_SZ + b1) * G_SZ;
    const float* bs = g_bsum + dir * G_SZ;
    #pragma unroll
    for (int nt = 0; nt < 16; nt++) {
        const int g = gb + nt * 8;
        const float2 bias = *(const float2*)(bs + g);
        *(float2*)(xg0 + g) = make_float2(acc[nt][0] + bias.x, acc[nt][1] + bias.y);
        *(float2*)(xg1 + g) = make_float2(acc[nt][2] + bias.x, acc[nt][3] + bias.y);
    }
}

// ---------------------------------------------------------------------------
// Persistent bidirectional LSTM, v4: single-pass fp16 mainloop (h hi only —
// mma count and A-fragment L2 traffic halved vs v3), depth-2 load pipeline,
// flat per-direction grid barrier, __expf epilogue, c in registers.
// ---------------------------------------------------------------------------
#define WS_U2   16384                        // 8*64*32 uint2 (131072 B)
#define PS_OFF  (WS_U2 * 2)
#define PSW     2432                         // 32 rows * stride 76
#define SMEM_BYTES (WS_U2 * 8 + 8 * PSW * 4) // 208896

__global__ __launch_bounds__(256, 1)
void lstm_persist_kernel(float* __restrict__ out, int write_hc)
{
    extern __shared__ float sm[];
    uint2* ws = (uint2*)sm;
    float* ps = sm + PS_OFF;

    const int dir = blockIdx.x >> 6;
    const int ct  = blockIdx.x & 63;
    const int tid = threadIdx.x;
    const int w   = tid >> 5;
    const int L   = tid & 31;

    {   // load W_hh fp16 slice into smem (once)
        const uint2* src = g_WhhB + ((size_t)(dir * 64 + ct) << 14);
        for (int i = tid; i < WS_U2; i += 256) ws[i] = src[i];
    }

    int bb[2], ul[2];
    #pragma unroll
    for (int p = 0; p < 2; p++) {
        const int cid = tid + (p << 8);
        bb[p] = cid >> 4;
        ul[p] = cid & 15;
    }
    float creg[2] = {0.0f, 0.0f};

    const size_t OUT_HC0 = (size_t)B_SZ * T_LEN * 2 * H_SZ;
    const size_t OUT_HC1 = OUT_HC0 + (size_t)B_SZ * 2 * H_SZ;
    unsigned spin_limit = 50000000u;

    __syncthreads();

    for (int s = 0; s < T_LEN; s++) {
        const int buf  = s & 1;
        const int nbuf = buf ^ 1;

        const size_t xgbase = ((size_t)dir * T_LEN + s) * B_SZ * G_SZ;
        float4 xgv[2];
        #pragma unroll
        for (int p = 0; p < 2; p++)
            xgv[p] = __ldcg((const float4*)(g_xg + xgbase
                            + (size_t)bb[p] * G_SZ + (ct << 6) + (ul[p] << 2)));

        if (s > 0) {
            float acc[2][8][4];
            #pragma unroll
            for (int mt = 0; mt < 2; mt++)
                #pragma unroll
                for (int nt = 0; nt < 8; nt++)
                    #pragma unroll
                    for (int i = 0; i < 4; i++) acc[mt][nt][i] = 0.0f;

            const uint4* afb = (const uint4*)g_hfragH
                               + ((size_t)(buf * 2 + dir) * 2) * (64 * 32);
            const int kk0 = w << 3;

            // depth-2 pipelined A-fragment loads (1 uint4 per (kk, mt))
            uint4 A[2][2];   // [stage][mt]
            #pragma unroll
            for (int st = 0; st < 2; st++)
                #pragma unroll
                for (int mt = 0; mt < 2; mt++)
                    A[st][mt] = __ldcg(afb + ((size_t)mt * 64 + kk0 + st) * 32 + L);

            #pragma unroll
            for (int i = 0; i < 8; i++) {
                const int st = i & 1;
                const int kk = kk0 + i;
                #pragma unroll
                for (int nt = 0; nt < 8; nt++) {
                    const uint2 wh = ws[((nt << 6) + kk) * 32 + L];
                    #pragma unroll
                    for (int mt = 0; mt < 2; mt++)
                        mma_f16(acc[mt][nt], A[st][mt].x, A[st][mt].y,
                                A[st][mt].z, A[st][mt].w, wh.x, wh.y);
                }
                if (i + 2 < 8) {
                    #pragma unroll
                    for (int mt = 0; mt < 2; mt++)
                        A[st][mt] = __ldcg(afb + ((size_t)mt * 64 + kk0 + i + 2) * 32
                                           + L);
                }
            }

            float* psw = ps + w * PSW;
            const int r  = L >> 2;
            const int g2 = (L & 3) * 2;
            #pragma unroll
            for (int mt = 0; mt < 2; mt++)
                #pragma unroll
                for (int nt = 0; nt < 8; nt++) {
                    const int row = mt * 16 + r;
                    const int g   = nt * 8 + g2;
                    *(float2*)&psw[row * 76 + g] =
                        make_float2(acc[mt][nt][0], acc[mt][nt][1]);
                    *(float2*)&psw[(row + 8) * 76 + g] =
                        make_float2(acc[mt][nt][2], acc[mt][nt][3]);
                }
        }
        __syncthreads();

        const int tphys = dir ? (T_LEN - 1 - s) : s;
        #pragma unroll
        for (int p = 0; p < 2; p++) {
            const int b = bb[p];
            const int u = ul[p];
            const int j = (ct << 4) + u;

            float4 v = make_float4(0.f, 0.f, 0.f, 0.f);
            if (s > 0) {
                #pragma unroll
                for (int ww = 0; ww < 8; ww++) {
                    const float4 q = *(const float4*)&ps[ww * PSW + b * 76 + u * 4];
                    v.x += q.x; v.y += q.y; v.z += q.z; v.w += q.w;
                }
            }

            const float iv = sigm(v.x + xgv[p].x);
            const float fv = sigm(v.y + xgv[p].y);
            const float gv = ftanh(v.z + xgv[p].z);
            const float ov = sigm(v.w + xgv[p].w);
            const float cc = fv * creg[p] + iv * gv;
            creg[p] = cc;
            const float h = ov * ftanh(cc);

            out[((size_t)b * T_LEN + tphys) * (2 * H_SZ) + (size_t)dir * H_SZ + j] = h;
            if (write_hc && s == T_LEN - 1) {
                out[OUT_HC0 + ((size_t)b * 2 + dir) * H_SZ + j] = h;
                out[OUT_HC1 + ((size_t)b * 2 + dir) * H_SZ + j] = cc;
            }

            const float hn = __shfl_down_sync(0xffffffffu, h, 1);
            if ((u & 1) == 0) {
                const unsigned hi = pack_h2(h, hn);
                const int mt    = b >> 4;
                const int rowin = b & 15;
                const int reg   = (rowin >> 3) + ((u >> 3) << 1);
                const int lane2 = (rowin & 7) * 4 + ((u & 7) >> 1);
                g_hfragH[(((size_t)(nbuf * 2 + dir) * 2 + mt) * 64 + ct) * 128
                         + lane2 * 4 + reg] = hi;
            }
        }

        // flat per-direction grid barrier (64 CTAs, 4 spread counters)
        __syncthreads();
        if (tid == 0) {
            unsigned* ctr = &g_arr[(dir * 4 + (ct & 3)) * 32];
            asm volatile("red.release.gpu.global.add.u32 [%0], 1;"
                         :: "l"(ctr) : "memory");
            const unsigned tgt = (unsigned)(s + 1) * 16;
            unsigned it = 0;
            for (;;) {
                unsigned done = 1;
                #pragma unroll
                for (int q = 0; q < 4; q++) {
                    unsigned vv;
                    asm volatile("ld.acquire.gpu.global.u32 %0, [%1];"
                                 : "=r"(vv) : "l"(&g_arr[(dir * 4 + q) * 32])
                                 : "memory");
                    done &= (unsigned)(vv >= tgt);
                }
                if (done) break;
                if (++it >= spin_limit) { spin_limit = 0; break; }
            }
        }
        __syncthreads();
    }
}

// ---------------------------------------------------------------------------
extern "C" void kernel_launch(void* const* d_in, const int* in_sizes, int n_in,
                              void* d_out, int out_size)
{
    const float* x     = (const float*)d_in[0];
    const float* Wf_ih = (const float*)d_in[1];
    const float* Wf_hh = (const float*)d_in[2];
    const float* bf_ih = (const float*)d_in[3];
    const float* bf_hh = (const float*)d_in[4];
    const float* Wb_ih = (const float*)d_in[5];
    const float* Wb_hh = (const float*)d_in[6];
    const float* bb_ih = (const float*)d_in[7];
    const float* bb_hh = (const float*)d_in[8];
    float* out = (float*)d_out;

    static int smem_set = 0;
    if (!smem_set) {
        cudaFuncSetAttribute(lstm_persist_kernel,
                             cudaFuncAttributeMaxDynamicSharedMemorySize,
                             SMEM_BYTES);
        cudaFuncSetAttribute(input_gemm_mma_kernel,
                             cudaFuncAttributeMaxDynamicSharedMemorySize,
                             GEMM_SMEM);
        smem_set = 1;
    }

    init_state_kernel<<<1, 256>>>();

    whh_prep_kernel<<<(2 * 64 * 8 * 64 * 32) / 256, 256>>>(Wf_hh, Wb_hh);
    wih_prep_kernel<<<(2 * 512 * 32 * 32) / 256, 256>>>(Wf_ih, Wb_ih);
    bsum_prep_kernel<<<(2 * G_SZ) / 256, 256>>>(bf_ih, bf_hh, bb_ih, bb_hh);
    xpack_kernel<<<(1024 * 32 * 32) / 256, 256>>>(x);

    input_gemm_mma_kernel<<<dim3(128, 32, 2), 256, GEMM_SMEM>>>();

    const long long full = (long long)B_SZ * T_LEN * 2 * H_SZ
                         + 2LL * B_SZ * 2 * H_SZ;
    const int write_hc = ((long long)out_size >= full) ? 1 : 0;

    lstm_persist_kernel<<<NCTA, 256, SMEM_BYTES>>>(out, write_hc);
}